// round 3
// baseline (speedup 1.0000x reference)
#include <cuda_runtime.h>
#include <cuda_bf16.h>
#include <math.h>

// GridGRU: N=32, T=512, D=1024, H=1024
// inputs: x (N,T,D), prev_ht (N,H), weight (2048,6144), bias (6144)
// outputs: h (N,T,D) then last_ht (N,H), concatenated in d_out.

#define NN 32
#define TT 512
#define DD 1024
#define HH 1024
#define MROWS (NN*TT)        // 16384
#define WLD 6144             // weight row stride
#define NB 128               // persistent scan blocks

// ---------------- scratch (device globals; no allocations allowed) ----------
__device__ float g_gates[(size_t)MROWS * 3072];  // 192 MB: x@Wxt + bt
__device__ float g_HT[(size_t)MROWS * HH];       // 64 MB: ht for all t
__device__ float g_hcur[NN * HH];                // current h (32x1024)
__device__ float g_U[NN * HH];                   // update gate u (per step)
__device__ float g_RH[NN * HH];                  // r*h (per step)
__device__ float g_UD[(size_t)MROWS * DD];       // 64 MB: ud
__device__ float g_RX[(size_t)MROWS * DD];       // 64 MB: rd*x
__device__ unsigned g_barcnt;                    // grid barrier counter

// ---------------- big SGEMM with fused epilogues -----------------------------
// C[M x Nc] = concatK(A0,A1)[M x K] @ W(view, row stride 6144) + epilogue
// EPI 0: gates -> out = acc + bias
// EPI 1: F1    -> s = sigmoid(acc+bias); col<1024 ? UD=s : RX = s*x
// EPI 2: F2    -> hc = tanh(acc+bias); out = x + UD*(hc-x)
template<int EPI>
__global__ void __launch_bounds__(256)
sgemm_epi(const float* __restrict__ A0,
          const float* __restrict__ A1,
          const float* __restrict__ W,
          const float* __restrict__ bias,
          const float* __restrict__ X,
          float* __restrict__ out,
          float* __restrict__ out2,
          const float* __restrict__ UD,
          int K, int ldc)
{
    __shared__ float As[8][128];
    __shared__ float Bs[8][128];

    const int tx = threadIdx.x;       // 0..15
    const int ty = threadIdx.y;       // 0..15
    const int t  = ty * 16 + tx;      // 0..255
    const int row0 = blockIdx.y * 128;
    const int col0 = blockIdx.x * 128;

    const int arow = t >> 1;
    const int acol = (t & 1) * 4;
    const int wrow = t >> 5;
    const int wcol = (t & 31) * 4;

    float acc[8][8];
#pragma unroll
    for (int i = 0; i < 8; i++)
#pragma unroll
        for (int j = 0; j < 8; j++) acc[i][j] = 0.f;

    for (int k0 = 0; k0 < K; k0 += 8) {
        int kk = k0 + acol;
        const float* Ap;
        if (kk < 1024) Ap = A0 + (long)(row0 + arow) * 1024 + kk;
        else           Ap = A1 + (long)(row0 + arow) * 1024 + (kk - 1024);
        float4 av = *(const float4*)Ap;
        As[acol + 0][arow] = av.x;
        As[acol + 1][arow] = av.y;
        As[acol + 2][arow] = av.z;
        As[acol + 3][arow] = av.w;

        float4 wv = *(const float4*)(W + (long)(k0 + wrow) * WLD + col0 + wcol);
        *(float4*)&Bs[wrow][wcol] = wv;

        __syncthreads();

#pragma unroll
        for (int k2 = 0; k2 < 8; k2++) {
            float a[8], b[8];
            *(float4*)&a[0] = *(const float4*)&As[k2][ty * 8];
            *(float4*)&a[4] = *(const float4*)&As[k2][ty * 8 + 4];
            *(float4*)&b[0] = *(const float4*)&Bs[k2][tx * 8];
            *(float4*)&b[4] = *(const float4*)&Bs[k2][tx * 8 + 4];
#pragma unroll
            for (int i = 0; i < 8; i++)
#pragma unroll
                for (int j = 0; j < 8; j++)
                    acc[i][j] = fmaf(a[i], b[j], acc[i][j]);
        }
        __syncthreads();
    }

#pragma unroll
    for (int i = 0; i < 8; i++) {
        long row = row0 + ty * 8 + i;
#pragma unroll
        for (int j = 0; j < 8; j++) {
            int col = col0 + tx * 8 + j;
            float v = acc[i][j] + bias[col];
            if (EPI == 0) {
                out[row * (long)ldc + col] = v;
            } else if (EPI == 1) {
                float s = 1.f / (1.f + expf(-v));
                if (col < 1024) {
                    out[row * 1024 + col] = s;
                } else {
                    int d = col - 1024;
                    out2[row * 1024 + d] = s * X[row * 1024 + d];
                }
            } else {
                float hc = tanhf(v);
                float xv = X[row * 1024 + col];
                out[row * 1024 + col] = xv + UD[row * 1024 + col] * (hc - xv);
            }
        }
    }
}

// ---------------- init: reset barrier + copy prev_ht -> hcur -----------------
__global__ void scan_init(const float* __restrict__ prev_ht, float* __restrict__ hcur)
{
    int i = blockIdx.x * 256 + threadIdx.x;
    if (i == 0) g_barcnt = 0;
    if (i < NN * HH) hcur[i] = prev_ht[i];
}

// ---------------- persistent scan --------------------------------------------
__device__ __forceinline__ void gridbar(unsigned target)
{
    __syncthreads();
    if (threadIdx.x == 0) {
        __threadfence();                 // release: drain my writes
        atomicAdd(&g_barcnt, 1u);
        while (*(volatile unsigned*)&g_barcnt < target) { }
        __threadfence();                 // acquire: gpu-scope fence flushes L1
    }
    __syncthreads();
}

// 128 blocks x 256 threads, all co-resident.
// Per step: phase1 computes GG = sigmoid(G[:, :2048] + h@Whtg): block bx owns
// cols bx*16..+15 (bx<64 -> U, else RH=r*h). phase2 computes hc/hn: block bx
// owns cols bx*8..+7. Weight slices persist in dynamic smem for all 512 steps.
extern __shared__ float dsm[];           // Ws1: 16384 floats, Ws2: 8192 floats
__global__ void __launch_bounds__(256, 1)
scan_persistent(const float* __restrict__ weight,
                const float* __restrict__ G,
                float* __restrict__ U,
                float* __restrict__ RH,
                float* __restrict__ hcur,
                float* __restrict__ HT)
{
    __shared__ float Hs[64][33];         // staged h/RH chunk (transposed)
    __shared__ float Ps[256 * 4];        // split-K partials

    float* Ws1 = dsm;                    // [1024][16]  Whtg slice
    float* Ws2 = dsm + 16384;            // [1024][8]   Whtc slice

    const int tid = threadIdx.x;
    const int bx  = blockIdx.x;
    const int row = tid & 31;            // batch row 0..31
    const int cg  = (tid >> 5) & 3;      // col group 0..3
    const int ks  = tid >> 7;            // K split 0/1

    // ---- load weight slices into smem (once) ----
#pragma unroll 4
    for (int i = 0; i < 64; i++) {
        int idx = tid + i * 256;         // 0..16383
        int k = idx >> 4, c = idx & 15;
        Ws1[idx] = weight[(long)(1024 + k) * WLD + bx * 16 + c];
    }
#pragma unroll 4
    for (int i = 0; i < 32; i++) {
        int idx = tid + i * 256;         // 0..8191
        int k = idx >> 3, c = idx & 7;
        Ws2[idx] = weight[(long)(1024 + k) * WLD + 2048 + bx * 8 + c];
    }
    __syncthreads();

    unsigned tgt = NB;

    for (int t = 0; t < TT; t++) {
        // ================= phase 1 =================
        // thread handles 4 cols: c0 = bx*16 + cg*4, K-half ks
        float4 acc = make_float4(0.f, 0.f, 0.f, 0.f);
        float4 gv = make_float4(0.f, 0.f, 0.f, 0.f);
        const int c0 = bx * 16 + cg * 4;
        if (ks == 0)
            gv = *(const float4*)&G[((long)row * TT + t) * 3072 + c0];

        for (int kc = 0; kc < 512; kc += 32) {
            // stage 64 k-values of hcur (both halves), transposed
#pragma unroll
            for (int i = 0; i < 8; i++) {
                int idx = tid + i * 256;            // 0..2047
                int kk = idx & 63, r = idx >> 6;
                int gk = (kk < 32) ? (kc + kk) : (512 + kc + kk - 32);
                Hs[kk][r] = hcur[r * 1024 + gk];
            }
            __syncthreads();
#pragma unroll
            for (int k2 = 0; k2 < 32; k2++) {
                float h = Hs[ks * 32 + k2][row];
                float4 w = *(const float4*)&Ws1[(ks * 512 + kc + k2) * 16 + cg * 4];
                acc.x = fmaf(h, w.x, acc.x);
                acc.y = fmaf(h, w.y, acc.y);
                acc.z = fmaf(h, w.z, acc.z);
                acc.w = fmaf(h, w.w, acc.w);
            }
            __syncthreads();
        }
        // combine split-K partials
        *(float4*)&Ps[tid * 4] = acc;
        __syncthreads();
        if (ks == 0) {
            float4 p = *(const float4*)&Ps[(tid + 128) * 4];
            acc.x += p.x; acc.y += p.y; acc.z += p.z; acc.w += p.w;
            float s0 = 1.f / (1.f + expf(-(acc.x + gv.x)));
            float s1 = 1.f / (1.f + expf(-(acc.y + gv.y)));
            float s2 = 1.f / (1.f + expf(-(acc.z + gv.z)));
            float s3 = 1.f / (1.f + expf(-(acc.w + gv.w)));
            if (c0 < 1024) {
                float4 o = make_float4(s0, s1, s2, s3);
                *(float4*)&U[row * 1024 + c0] = o;
            } else {
                int d = c0 - 1024;
                float4 hv = *(const float4*)&hcur[row * 1024 + d];
                float4 o = make_float4(s0 * hv.x, s1 * hv.y, s2 * hv.z, s3 * hv.w);
                *(float4*)&RH[row * 1024 + d] = o;
            }
        }

        gridbar(tgt); tgt += NB;         // barrier A

        // ================= phase 2 =================
        // thread handles 2 cols: d0 = bx*8 + cg*2, K-half ks
        float a0 = 0.f, a1 = 0.f;
        const int d0 = bx * 8 + cg * 2;
        float2 gv2 = make_float2(0.f, 0.f);
        if (ks == 0)
            gv2 = *(const float2*)&G[((long)row * TT + t) * 3072 + 2048 + d0];

        for (int kc = 0; kc < 512; kc += 32) {
#pragma unroll
            for (int i = 0; i < 8; i++) {
                int idx = tid + i * 256;
                int kk = idx & 63, r = idx >> 6;
                int gk = (kk < 32) ? (kc + kk) : (512 + kc + kk - 32);
                Hs[kk][r] = RH[r * 1024 + gk];
            }
            __syncthreads();
#pragma unroll
            for (int k2 = 0; k2 < 32; k2++) {
                float h = Hs[ks * 32 + k2][row];
                float2 w = *(const float2*)&Ws2[(ks * 512 + kc + k2) * 8 + cg * 2];
                a0 = fmaf(h, w.x, a0);
                a1 = fmaf(h, w.y, a1);
            }
            __syncthreads();
        }
        Ps[tid * 2 + 0] = a0;
        Ps[tid * 2 + 1] = a1;
        __syncthreads();
        if (ks == 0) {
            a0 += Ps[(tid + 128) * 2 + 0];
            a1 += Ps[(tid + 128) * 2 + 1];
            float hc0 = tanhf(a0 + gv2.x);
            float hc1 = tanhf(a1 + gv2.y);
            float2 hp = *(const float2*)&hcur[row * 1024 + d0];
            float2 uu = *(const float2*)&U[row * 1024 + d0];
            float2 hn;
            hn.x = hp.x + uu.x * (hc0 - hp.x);
            hn.y = hp.y + uu.y * (hc1 - hp.y);
            *(float2*)&hcur[row * 1024 + d0] = hn;
            *(float2*)&HT[((long)row * TT + t) * 1024 + d0] = hn;
        }

        gridbar(tgt); tgt += NB;         // barrier B
    }
}

__global__ void copy_last(const float* __restrict__ HT, float* __restrict__ out)
{
    int i = blockIdx.x * 256 + threadIdx.x;   // 0..32767
    int n = i >> 10, c = i & 1023;
    out[i] = HT[((long)n * TT + (TT - 1)) * 1024 + c];
}

// ---------------- launch ------------------------------------------------------
extern "C" void kernel_launch(void* const* d_in, const int* in_sizes, int n_in,
                              void* d_out, int out_size)
{
    const float* x       = (const float*)d_in[0];
    const float* prev_ht = (const float*)d_in[1];
    const float* weight  = (const float*)d_in[2];
    const float* bias    = (const float*)d_in[3];
    float* out = (float*)d_out;

    float *G, *HT, *HC, *U, *RH, *UD, *RX;
    cudaGetSymbolAddress((void**)&G,  g_gates);
    cudaGetSymbolAddress((void**)&HT, g_HT);
    cudaGetSymbolAddress((void**)&HC, g_hcur);
    cudaGetSymbolAddress((void**)&U,  g_U);
    cudaGetSymbolAddress((void**)&RH, g_RH);
    cudaGetSymbolAddress((void**)&UD, g_UD);
    cudaGetSymbolAddress((void**)&RX, g_RX);

    static int smem_set = 0;
    if (!smem_set) {
        cudaFuncSetAttribute(scan_persistent,
                             cudaFuncAttributeMaxDynamicSharedMemorySize,
                             (16384 + 8192) * sizeof(float));
        smem_set = 1;
    }

    dim3 thr(16, 16);

    // gates = x @ Wxt + bt   (M=16384, Nc=3072, K=1024)
    sgemm_epi<0><<<dim3(3072 / 128, MROWS / 128), thr>>>(
        x, nullptr, weight, bias, nullptr, G, nullptr, nullptr, 1024, 3072);

    // sequential scan: one persistent kernel
    scan_init<<<128, 256>>>(prev_ht, HC);
    scan_persistent<<<NB, 256, (16384 + 8192) * sizeof(float)>>>(
        weight, G, U, RH, HC, HT);

    // F1: grd = sigmoid(bd[:2D] + x@Wxd[:,:2D] + ht@Whd[:,:2D]) -> UD, RX
    sgemm_epi<1><<<dim3(2048 / 128, MROWS / 128), thr>>>(
        x, HT, weight + 3072, bias + 3072, x, UD, RX, nullptr, 2048, 2048);

    // F2: hcd = tanh(bd[2D:] + ht@Whd[:,2D:] + (rd*x)@Wxd[:,2D:]);
    //     h = x + ud*(hcd - x)
    sgemm_epi<2><<<dim3(1024 / 128, MROWS / 128), thr>>>(
        RX, HT, weight + 5120, bias + 5120, x, out, nullptr, UD, 2048, 1024);

    // last_ht
    copy_last<<<128, 256>>>(HT, out + (size_t)MROWS * 1024);
}

// round 4
// speedup vs baseline: 1.0874x; 1.0874x over previous
#include <cuda_runtime.h>
#include <cuda_bf16.h>
#include <math.h>
#include <stdint.h>

// GridGRU: N=32, T=512, D=1024, H=1024
// inputs: x (N,T,D), prev_ht (N,H), weight (2048,6144), bias (6144)
// outputs: h (N,T,D) then last_ht (N,H), concatenated in d_out.

#define NN 32
#define TT 512
#define DD 1024
#define HH 1024
#define MROWS (NN*TT)        // 16384
#define WLD 6144             // weight row stride
#define NB 128               // persistent scan blocks
#define KPAD 36              // smem k stride (bank-conflict-free)

// ---------------- scratch (device globals; no allocations allowed) ----------
__device__ float g_gates[(size_t)MROWS * 3072];  // 192 MB
__device__ float g_HT[(size_t)MROWS * HH];       // 64 MB
__device__ float g_hcur[NN * HH];
__device__ float g_U[NN * HH];
__device__ float g_RH[NN * HH];
__device__ float g_UD[(size_t)MROWS * DD];       // 64 MB
__device__ float g_RX[(size_t)MROWS * DD];       // 64 MB
__device__ unsigned g_barcnt;

// ---------------- bf16-split tensor-core GEMM with fused epilogues ----------
__device__ __forceinline__ void mma16816(float* c, const uint32_t* a, const uint32_t* b)
{
    asm volatile(
        "mma.sync.aligned.m16n8k16.row.col.f32.bf16.bf16.f32 "
        "{%0,%1,%2,%3}, {%4,%5,%6,%7}, {%8,%9}, {%0,%1,%2,%3};\n"
        : "+f"(c[0]), "+f"(c[1]), "+f"(c[2]), "+f"(c[3])
        : "r"(a[0]), "r"(a[1]), "r"(a[2]), "r"(a[3]), "r"(b[0]), "r"(b[1]));
}

// C[M x Nc] = concatK(A0,A1)[M x K] @ W(row stride 6144) + epilogue
// EPI 0: gates -> out = acc + bias
// EPI 1: F1    -> s = sigmoid(acc+bias); col<1024 ? UD=s : RX = s*x
// EPI 2: F2    -> hc = tanh(acc+bias); out = x + UD*(hc-x)
template<int EPI>
__global__ void __launch_bounds__(256)
mma_gemm(const float* __restrict__ A0,
         const float* __restrict__ A1,
         const float* __restrict__ W,
         const float* __restrict__ bias,
         const float* __restrict__ X,
         float* __restrict__ out,
         float* __restrict__ out2,
         const float* __restrict__ UD,
         int K, int ldc)
{
    __shared__ __nv_bfloat16 As_hi[128][KPAD], As_lo[128][KPAD];
    __shared__ __nv_bfloat16 Bs_hi[128][KPAD], Bs_lo[128][KPAD];

    const int tid  = threadIdx.x;
    const int lane = tid & 31, warp = tid >> 5;
    const int warpM = warp & 1, warpN = warp >> 1;   // 2 x 4 warp grid
    const int g = lane >> 2, tig = lane & 3;
    const int row0 = blockIdx.y * 128, col0 = blockIdx.x * 128;

    const int rA = warpM * 64;   // warp row base in tile
    const int cB = warpN * 32;   // warp col base in tile

    // A tile staging: thread covers row ar, cols ac0 + q*4 (float4 each)
    const int ar  = tid >> 1;
    const int ac0 = (tid & 1) * 16;

    float acc[4][4][4];
#pragma unroll
    for (int i = 0; i < 4; i++)
#pragma unroll
        for (int j = 0; j < 4; j++)
#pragma unroll
            for (int e = 0; e < 4; e++) acc[i][j][e] = 0.f;

    float4 av[4], bv[4];

    // ---- prologue: load tile k0=0 into regs ----
#pragma unroll
    for (int q = 0; q < 4; q++) {
        int kk = ac0 + q * 4;
        const float* Ap = (kk < 1024) ? A0 + (long)(row0 + ar) * 1024 + kk
                                      : A1 + (long)(row0 + ar) * 1024 + (kk - 1024);
        av[q] = *(const float4*)Ap;
    }
#pragma unroll
    for (int q = 0; q < 4; q++) {
        int f4 = tid + q * 256;
        int kr = f4 >> 5, nc = (f4 & 31) * 4;
        bv[q] = *(const float4*)(W + (long)kr * WLD + col0 + nc);
    }

    for (int k0 = 0; k0 < K; k0 += 32) {
        __syncthreads();   // previous compute done reading smem

        // ---- convert regs -> smem (hi/lo split) ----
#pragma unroll
        for (int q = 0; q < 4; q++) {
            int c = ac0 + q * 4;
            float vals[4] = {av[q].x, av[q].y, av[q].z, av[q].w};
#pragma unroll
            for (int e = 0; e < 4; e++) {
                __nv_bfloat16 h = __float2bfloat16(vals[e]);
                As_hi[ar][c + e] = h;
                As_lo[ar][c + e] = __float2bfloat16(vals[e] - __bfloat162float(h));
            }
        }
#pragma unroll
        for (int q = 0; q < 4; q++) {
            int f4 = tid + q * 256;
            int kr = f4 >> 5, nc = (f4 & 31) * 4;
            float vals[4] = {bv[q].x, bv[q].y, bv[q].z, bv[q].w};
#pragma unroll
            for (int e = 0; e < 4; e++) {
                __nv_bfloat16 h = __float2bfloat16(vals[e]);
                Bs_hi[nc + e][kr] = h;
                Bs_lo[nc + e][kr] = __float2bfloat16(vals[e] - __bfloat162float(h));
            }
        }
        __syncthreads();

        // ---- prefetch next tile into regs (overlaps with MMA below) ----
        if (k0 + 32 < K) {
#pragma unroll
            for (int q = 0; q < 4; q++) {
                int kk = k0 + 32 + ac0 + q * 4;
                const float* Ap = (kk < 1024) ? A0 + (long)(row0 + ar) * 1024 + kk
                                              : A1 + (long)(row0 + ar) * 1024 + (kk - 1024);
                av[q] = *(const float4*)Ap;
            }
#pragma unroll
            for (int q = 0; q < 4; q++) {
                int f4 = tid + q * 256;
                int kr = f4 >> 5, nc = (f4 & 31) * 4;
                bv[q] = *(const float4*)(W + (long)(k0 + 32 + kr) * WLD + col0 + nc);
            }
        }

        // ---- MMA over the staged 128x32 tiles ----
#pragma unroll
        for (int kk = 0; kk < 32; kk += 16) {
            uint32_t ah[4][4], al[4][4], bh[4][2], bl[4][2];
#pragma unroll
            for (int i = 0; i < 4; i++) {
                int r = rA + i * 16 + g;
                int c = kk + tig * 2;
                ah[i][0] = *(const uint32_t*)&As_hi[r][c];
                ah[i][1] = *(const uint32_t*)&As_hi[r + 8][c];
                ah[i][2] = *(const uint32_t*)&As_hi[r][c + 8];
                ah[i][3] = *(const uint32_t*)&As_hi[r + 8][c + 8];
                al[i][0] = *(const uint32_t*)&As_lo[r][c];
                al[i][1] = *(const uint32_t*)&As_lo[r + 8][c];
                al[i][2] = *(const uint32_t*)&As_lo[r][c + 8];
                al[i][3] = *(const uint32_t*)&As_lo[r + 8][c + 8];
            }
#pragma unroll
            for (int j = 0; j < 4; j++) {
                int n = cB + j * 8 + g;
                int c = kk + tig * 2;
                bh[j][0] = *(const uint32_t*)&Bs_hi[n][c];
                bh[j][1] = *(const uint32_t*)&Bs_hi[n][c + 8];
                bl[j][0] = *(const uint32_t*)&Bs_lo[n][c];
                bl[j][1] = *(const uint32_t*)&Bs_lo[n][c + 8];
            }
#pragma unroll
            for (int i = 0; i < 4; i++)
#pragma unroll
                for (int j = 0; j < 4; j++) {
                    mma16816(acc[i][j], ah[i], bh[j]);
                    mma16816(acc[i][j], ah[i], bl[j]);
                    mma16816(acc[i][j], al[i], bh[j]);
                }
        }
    }

    // ---- epilogue ----
    auto epi2 = [&](long row, int col, float v0, float v1) {
        v0 += bias[col]; v1 += bias[col + 1];
        if (EPI == 0) {
            out[row * (long)ldc + col]     = v0;
            out[row * (long)ldc + col + 1] = v1;
        } else if (EPI == 1) {
            float s0 = 1.f / (1.f + expf(-v0));
            float s1 = 1.f / (1.f + expf(-v1));
            if (col < 1024) {
                out[row * 1024 + col]     = s0;
                out[row * 1024 + col + 1] = s1;
            } else {
                int d = col - 1024;
                out2[row * 1024 + d]     = s0 * X[row * 1024 + d];
                out2[row * 1024 + d + 1] = s1 * X[row * 1024 + d + 1];
            }
        } else {
            float hc0 = tanhf(v0), hc1 = tanhf(v1);
            float x0 = X[row * 1024 + col], x1 = X[row * 1024 + col + 1];
            out[row * 1024 + col]     = x0 + UD[row * 1024 + col] * (hc0 - x0);
            out[row * 1024 + col + 1] = x1 + UD[row * 1024 + col + 1] * (hc1 - x1);
        }
    };

#pragma unroll
    for (int i = 0; i < 4; i++) {
        long r = row0 + rA + i * 16 + g;
#pragma unroll
        for (int j = 0; j < 4; j++) {
            int cc = col0 + cB + j * 8 + tig * 2;
            epi2(r,     cc, acc[i][j][0], acc[i][j][1]);
            epi2(r + 8, cc, acc[i][j][2], acc[i][j][3]);
        }
    }
}

// ---------------- init: reset barrier + copy prev_ht -> hcur -----------------
__global__ void scan_init(const float* __restrict__ prev_ht, float* __restrict__ hcur)
{
    int i = blockIdx.x * 256 + threadIdx.x;
    if (i == 0) g_barcnt = 0;
    if (i < NN * HH) hcur[i] = prev_ht[i];
}

// ---------------- persistent scan --------------------------------------------
__device__ __forceinline__ void gridbar(unsigned target)
{
    __syncthreads();
    if (threadIdx.x == 0) {
        __threadfence();
        atomicAdd(&g_barcnt, 1u);
        while (*(volatile unsigned*)&g_barcnt < target) { }
        __threadfence();
    }
    __syncthreads();
}

extern __shared__ float dsm[];           // Ws1: 16384 floats, Ws2: 8192 floats
__global__ void __launch_bounds__(256, 1)
scan_persistent(const float* __restrict__ weight,
                const float* __restrict__ G,
                float* __restrict__ U,
                float* __restrict__ RH,
                float* __restrict__ hcur,
                float* __restrict__ HT)
{
    __shared__ float Hs[64][33];
    __shared__ float Ps[256 * 4];

    float* Ws1 = dsm;                    // [1024][16]  Whtg slice
    float* Ws2 = dsm + 16384;            // [1024][8]   Whtc slice

    const int tid = threadIdx.x;
    const int bx  = blockIdx.x;
    const int row = tid & 31;
    const int cg  = (tid >> 5) & 3;
    const int ks  = tid >> 7;

#pragma unroll 4
    for (int i = 0; i < 64; i++) {
        int idx = tid + i * 256;
        int k = idx >> 4, c = idx & 15;
        Ws1[idx] = weight[(long)(1024 + k) * WLD + bx * 16 + c];
    }
#pragma unroll 4
    for (int i = 0; i < 32; i++) {
        int idx = tid + i * 256;
        int k = idx >> 3, c = idx & 7;
        Ws2[idx] = weight[(long)(1024 + k) * WLD + 2048 + bx * 8 + c];
    }
    __syncthreads();

    unsigned tgt = NB;

    for (int t = 0; t < TT; t++) {
        // ================= phase 1 =================
        float4 acc = make_float4(0.f, 0.f, 0.f, 0.f);
        float4 gv = make_float4(0.f, 0.f, 0.f, 0.f);
        const int c0 = bx * 16 + cg * 4;
        if (ks == 0)
            gv = *(const float4*)&G[((long)row * TT + t) * 3072 + c0];

        for (int kc = 0; kc < 512; kc += 32) {
#pragma unroll
            for (int i = 0; i < 8; i++) {
                int idx = tid + i * 256;
                int kk = idx & 63, r = idx >> 6;
                int gk = (kk < 32) ? (kc + kk) : (512 + kc + kk - 32);
                Hs[kk][r] = hcur[r * 1024 + gk];
            }
            __syncthreads();
#pragma unroll
            for (int k2 = 0; k2 < 32; k2++) {
                float h = Hs[ks * 32 + k2][row];
                float4 w = *(const float4*)&Ws1[(ks * 512 + kc + k2) * 16 + cg * 4];
                acc.x = fmaf(h, w.x, acc.x);
                acc.y = fmaf(h, w.y, acc.y);
                acc.z = fmaf(h, w.z, acc.z);
                acc.w = fmaf(h, w.w, acc.w);
            }
            __syncthreads();
        }
        *(float4*)&Ps[tid * 4] = acc;
        __syncthreads();
        if (ks == 0) {
            float4 p = *(const float4*)&Ps[(tid + 128) * 4];
            acc.x += p.x; acc.y += p.y; acc.z += p.z; acc.w += p.w;
            float s0 = 1.f / (1.f + expf(-(acc.x + gv.x)));
            float s1 = 1.f / (1.f + expf(-(acc.y + gv.y)));
            float s2 = 1.f / (1.f + expf(-(acc.z + gv.z)));
            float s3 = 1.f / (1.f + expf(-(acc.w + gv.w)));
            if (c0 < 1024) {
                float4 o = make_float4(s0, s1, s2, s3);
                *(float4*)&U[row * 1024 + c0] = o;
            } else {
                int d = c0 - 1024;
                float4 hv = *(const float4*)&hcur[row * 1024 + d];
                float4 o = make_float4(s0 * hv.x, s1 * hv.y, s2 * hv.z, s3 * hv.w);
                *(float4*)&RH[row * 1024 + d] = o;
            }
        }

        gridbar(tgt); tgt += NB;

        // ================= phase 2 =================
        float a0 = 0.f, a1 = 0.f;
        const int d0 = bx * 8 + cg * 2;
        float2 gv2 = make_float2(0.f, 0.f);
        if (ks == 0)
            gv2 = *(const float2*)&G[((long)row * TT + t) * 3072 + 2048 + d0];

        for (int kc = 0; kc < 512; kc += 32) {
#pragma unroll
            for (int i = 0; i < 8; i++) {
                int idx = tid + i * 256;
                int kk = idx & 63, r = idx >> 6;
                int gk = (kk < 32) ? (kc + kk) : (512 + kc + kk - 32);
                Hs[kk][r] = RH[r * 1024 + gk];
            }
            __syncthreads();
#pragma unroll
            for (int k2 = 0; k2 < 32; k2++) {
                float h = Hs[ks * 32 + k2][row];
                float2 w = *(const float2*)&Ws2[(ks * 512 + kc + k2) * 8 + cg * 2];
                a0 = fmaf(h, w.x, a0);
                a1 = fmaf(h, w.y, a1);
            }
            __syncthreads();
        }
        Ps[tid * 2 + 0] = a0;
        Ps[tid * 2 + 1] = a1;
        __syncthreads();
        if (ks == 0) {
            a0 += Ps[(tid + 128) * 2 + 0];
            a1 += Ps[(tid + 128) * 2 + 1];
            float hc0 = tanhf(a0 + gv2.x);
            float hc1 = tanhf(a1 + gv2.y);
            float2 hp = *(const float2*)&hcur[row * 1024 + d0];
            float2 uu = *(const float2*)&U[row * 1024 + d0];
            float2 hn;
            hn.x = hp.x + uu.x * (hc0 - hp.x);
            hn.y = hp.y + uu.y * (hc1 - hp.y);
            *(float2*)&hcur[row * 1024 + d0] = hn;
            *(float2*)&HT[((long)row * TT + t) * 1024 + d0] = hn;
        }

        gridbar(tgt); tgt += NB;
    }
}

__global__ void copy_last(const float* __restrict__ HT, float* __restrict__ out)
{
    int i = blockIdx.x * 256 + threadIdx.x;
    int n = i >> 10, c = i & 1023;
    out[i] = HT[((long)n * TT + (TT - 1)) * 1024 + c];
}

// ---------------- launch ------------------------------------------------------
extern "C" void kernel_launch(void* const* d_in, const int* in_sizes, int n_in,
                              void* d_out, int out_size)
{
    const float* x       = (const float*)d_in[0];
    const float* prev_ht = (const float*)d_in[1];
    const float* weight  = (const float*)d_in[2];
    const float* bias    = (const float*)d_in[3];
    float* out = (float*)d_out;

    float *G, *HT, *HC, *U, *RH, *UD, *RX;
    cudaGetSymbolAddress((void**)&G,  g_gates);
    cudaGetSymbolAddress((void**)&HT, g_HT);
    cudaGetSymbolAddress((void**)&HC, g_hcur);
    cudaGetSymbolAddress((void**)&U,  g_U);
    cudaGetSymbolAddress((void**)&RH, g_RH);
    cudaGetSymbolAddress((void**)&UD, g_UD);
    cudaGetSymbolAddress((void**)&RX, g_RX);

    static int smem_set = 0;
    if (!smem_set) {
        cudaFuncSetAttribute(scan_persistent,
                             cudaFuncAttributeMaxDynamicSharedMemorySize,
                             (16384 + 8192) * sizeof(float));
        smem_set = 1;
    }

    // gates = x @ Wxt + bt   (M=16384, Nc=3072, K=1024)
    mma_gemm<0><<<dim3(3072 / 128, MROWS / 128), 256>>>(
        x, nullptr, weight, bias, nullptr, G, nullptr, nullptr, 1024, 3072);

    // sequential scan: one persistent kernel
    scan_init<<<128, 256>>>(prev_ht, HC);
    scan_persistent<<<NB, 256, (16384 + 8192) * sizeof(float)>>>(
        weight, G, U, RH, HC, HT);

    // F1: grd = sigmoid(bd[:2D] + x@Wxd[:,:2D] + ht@Whd[:,:2D]) -> UD, RX
    mma_gemm<1><<<dim3(2048 / 128, MROWS / 128), 256>>>(
        x, HT, weight + 3072, bias + 3072, x, UD, RX, nullptr, 2048, 2048);

    // F2: hcd = tanh(bd[2D:] + ht@Whd[:,2D:] + (rd*x)@Wxd[:,2D:]);
    //     h = x + ud*(hcd - x)
    mma_gemm<2><<<dim3(1024 / 128, MROWS / 128), 256>>>(
        RX, HT, weight + 5120, bias + 5120, x, out, nullptr, UD, 2048, 1024);

    // last_ht
    copy_last<<<128, 256>>>(HT, out + (size_t)MROWS * 1024);
}

// round 5
// speedup vs baseline: 2.0999x; 1.9311x over previous
#include <cuda_runtime.h>
#include <cuda_bf16.h>
#include <math.h>
#include <stdint.h>

// GridGRU: N=32, T=512, D=1024, H=1024
// inputs: x (N,T,D), prev_ht (N,H), weight (2048,6144), bias (6144)
// outputs: h (N,T,D) then last_ht (N,H), concatenated in d_out.

#define NN 32
#define TT 512
#define DD 1024
#define HH 1024
#define MROWS (NN*TT)        // 16384
#define WLD 6144             // weight row stride
#define NB 128               // persistent scan blocks
#define KPAD 36              // big-GEMM smem k stride
#define WSP 1032             // scan weight smem k stride (bf16, conflict-free)
#define HSP 520              // scan activation smem k stride (bf16)

// ---------------- scratch (device globals; no allocations allowed) ----------
__device__ float g_gates[(size_t)MROWS * 3072];  // 192 MB
__device__ float g_HT[(size_t)MROWS * HH];       // 64 MB
__device__ float g_hcur[NN * HH];                // fp32 master h
__device__ float g_U[NN * HH];
__device__ float g_UD[(size_t)MROWS * DD];       // 64 MB
__device__ float g_RX[(size_t)MROWS * DD];       // 64 MB
__device__ __nv_bfloat16 g_h_hi[NN * HH], g_h_lo[NN * HH];
__device__ __nv_bfloat16 g_rh_hi[NN * HH], g_rh_lo[NN * HH];
__device__ unsigned g_barcnt;

// ---------------- bf16-split tensor-core MMA -------------------------------
__device__ __forceinline__ void mma16816(float* c, const uint32_t* a, const uint32_t* b)
{
    asm volatile(
        "mma.sync.aligned.m16n8k16.row.col.f32.bf16.bf16.f32 "
        "{%0,%1,%2,%3}, {%4,%5,%6,%7}, {%8,%9}, {%0,%1,%2,%3};\n"
        : "+f"(c[0]), "+f"(c[1]), "+f"(c[2]), "+f"(c[3])
        : "r"(a[0]), "r"(a[1]), "r"(a[2]), "r"(a[3]), "r"(b[0]), "r"(b[1]));
}

// ---------------- big GEMM with fused epilogues (unchanged from R3) --------
template<int EPI>
__global__ void __launch_bounds__(256)
mma_gemm(const float* __restrict__ A0,
         const float* __restrict__ A1,
         const float* __restrict__ W,
         const float* __restrict__ bias,
         const float* __restrict__ X,
         float* __restrict__ out,
         float* __restrict__ out2,
         const float* __restrict__ UD,
         int K, int ldc)
{
    __shared__ __nv_bfloat16 As_hi[128][KPAD], As_lo[128][KPAD];
    __shared__ __nv_bfloat16 Bs_hi[128][KPAD], Bs_lo[128][KPAD];

    const int tid  = threadIdx.x;
    const int lane = tid & 31, warp = tid >> 5;
    const int warpM = warp & 1, warpN = warp >> 1;
    const int g = lane >> 2, tig = lane & 3;
    const int row0 = blockIdx.y * 128, col0 = blockIdx.x * 128;

    const int rA = warpM * 64;
    const int cB = warpN * 32;
    const int ar  = tid >> 1;
    const int ac0 = (tid & 1) * 16;

    float acc[4][4][4];
#pragma unroll
    for (int i = 0; i < 4; i++)
#pragma unroll
        for (int j = 0; j < 4; j++)
#pragma unroll
            for (int e = 0; e < 4; e++) acc[i][j][e] = 0.f;

    float4 av[4], bv[4];

#pragma unroll
    for (int q = 0; q < 4; q++) {
        int kk = ac0 + q * 4;
        const float* Ap = (kk < 1024) ? A0 + (long)(row0 + ar) * 1024 + kk
                                      : A1 + (long)(row0 + ar) * 1024 + (kk - 1024);
        av[q] = *(const float4*)Ap;
    }
#pragma unroll
    for (int q = 0; q < 4; q++) {
        int f4 = tid + q * 256;
        int kr = f4 >> 5, nc = (f4 & 31) * 4;
        bv[q] = *(const float4*)(W + (long)kr * WLD + col0 + nc);
    }

    for (int k0 = 0; k0 < K; k0 += 32) {
        __syncthreads();
#pragma unroll
        for (int q = 0; q < 4; q++) {
            int c = ac0 + q * 4;
            float vals[4] = {av[q].x, av[q].y, av[q].z, av[q].w};
#pragma unroll
            for (int e = 0; e < 4; e++) {
                __nv_bfloat16 h = __float2bfloat16(vals[e]);
                As_hi[ar][c + e] = h;
                As_lo[ar][c + e] = __float2bfloat16(vals[e] - __bfloat162float(h));
            }
        }
#pragma unroll
        for (int q = 0; q < 4; q++) {
            int f4 = tid + q * 256;
            int kr = f4 >> 5, nc = (f4 & 31) * 4;
            float vals[4] = {bv[q].x, bv[q].y, bv[q].z, bv[q].w};
#pragma unroll
            for (int e = 0; e < 4; e++) {
                __nv_bfloat16 h = __float2bfloat16(vals[e]);
                Bs_hi[nc + e][kr] = h;
                Bs_lo[nc + e][kr] = __float2bfloat16(vals[e] - __bfloat162float(h));
            }
        }
        __syncthreads();

        if (k0 + 32 < K) {
#pragma unroll
            for (int q = 0; q < 4; q++) {
                int kk = k0 + 32 + ac0 + q * 4;
                const float* Ap = (kk < 1024) ? A0 + (long)(row0 + ar) * 1024 + kk
                                              : A1 + (long)(row0 + ar) * 1024 + (kk - 1024);
                av[q] = *(const float4*)Ap;
            }
#pragma unroll
            for (int q = 0; q < 4; q++) {
                int f4 = tid + q * 256;
                int kr = f4 >> 5, nc = (f4 & 31) * 4;
                bv[q] = *(const float4*)(W + (long)(k0 + 32 + kr) * WLD + col0 + nc);
            }
        }

#pragma unroll
        for (int kk = 0; kk < 32; kk += 16) {
            uint32_t ah[4][4], al[4][4], bh[4][2], bl[4][2];
#pragma unroll
            for (int i = 0; i < 4; i++) {
                int r = rA + i * 16 + g;
                int c = kk + tig * 2;
                ah[i][0] = *(const uint32_t*)&As_hi[r][c];
                ah[i][1] = *(const uint32_t*)&As_hi[r + 8][c];
                ah[i][2] = *(const uint32_t*)&As_hi[r][c + 8];
                ah[i][3] = *(const uint32_t*)&As_hi[r + 8][c + 8];
                al[i][0] = *(const uint32_t*)&As_lo[r][c];
                al[i][1] = *(const uint32_t*)&As_lo[r + 8][c];
                al[i][2] = *(const uint32_t*)&As_lo[r][c + 8];
                al[i][3] = *(const uint32_t*)&As_lo[r + 8][c + 8];
            }
#pragma unroll
            for (int j = 0; j < 4; j++) {
                int n = cB + j * 8 + g;
                int c = kk + tig * 2;
                bh[j][0] = *(const uint32_t*)&Bs_hi[n][c];
                bh[j][1] = *(const uint32_t*)&Bs_hi[n][c + 8];
                bl[j][0] = *(const uint32_t*)&Bs_lo[n][c];
                bl[j][1] = *(const uint32_t*)&Bs_lo[n][c + 8];
            }
#pragma unroll
            for (int i = 0; i < 4; i++)
#pragma unroll
                for (int j = 0; j < 4; j++) {
                    mma16816(acc[i][j], ah[i], bh[j]);
                    mma16816(acc[i][j], ah[i], bl[j]);
                    mma16816(acc[i][j], al[i], bh[j]);
                }
        }
    }

    auto epi2 = [&](long row, int col, float v0, float v1) {
        v0 += bias[col]; v1 += bias[col + 1];
        if (EPI == 0) {
            out[row * (long)ldc + col]     = v0;
            out[row * (long)ldc + col + 1] = v1;
        } else if (EPI == 1) {
            float s0 = 1.f / (1.f + expf(-v0));
            float s1 = 1.f / (1.f + expf(-v1));
            if (col < 1024) {
                out[row * 1024 + col]     = s0;
                out[row * 1024 + col + 1] = s1;
            } else {
                int d = col - 1024;
                out2[row * 1024 + d]     = s0 * X[row * 1024 + d];
                out2[row * 1024 + d + 1] = s1 * X[row * 1024 + d + 1];
            }
        } else {
            float hc0 = tanhf(v0), hc1 = tanhf(v1);
            float x0 = X[row * 1024 + col], x1 = X[row * 1024 + col + 1];
            out[row * 1024 + col]     = x0 + UD[row * 1024 + col] * (hc0 - x0);
            out[row * 1024 + col + 1] = x1 + UD[row * 1024 + col + 1] * (hc1 - x1);
        }
    };

#pragma unroll
    for (int i = 0; i < 4; i++) {
        long r = row0 + rA + i * 16 + g;
#pragma unroll
        for (int j = 0; j < 4; j++) {
            int cc = col0 + cB + j * 8 + tig * 2;
            epi2(r,     cc, acc[i][j][0], acc[i][j][1]);
            epi2(r + 8, cc, acc[i][j][2], acc[i][j][3]);
        }
    }
}

// ---------------- init: reset barrier + hcur/h_hi/h_lo ----------------------
__global__ void scan_init(const float* __restrict__ prev_ht)
{
    int i = blockIdx.x * 256 + threadIdx.x;   // exactly 32768
    if (i == 0) g_barcnt = 0;
    float v = prev_ht[i];
    g_hcur[i] = v;
    __nv_bfloat16 hi = __float2bfloat16(v);
    g_h_hi[i] = hi;
    g_h_lo[i] = __float2bfloat16(v - __bfloat162float(hi));
}

// ---------------- grid barrier: release-add + acquire-poll ------------------
__device__ __forceinline__ void gridbar(unsigned target)
{
    __syncthreads();
    if (threadIdx.x == 0) {
        asm volatile("red.release.gpu.global.add.u32 [%0], 1;"
                     :: "l"(&g_barcnt) : "memory");
        unsigned v;
        do {
            asm volatile("ld.acquire.gpu.global.u32 %0, [%1];"
                         : "=r"(v) : "l"(&g_barcnt) : "memory");
        } while (v < target);
    }
    __syncthreads();
}

// ---------------- persistent tensor-core scan --------------------------------
// 128 blocks x 256 threads (8 warps). Block bx owns:
//   phase1: cols bx*16..+15 of the 32x2048 gate GEMM (bx<64 -> U, else RH)
//   phase2: cols bx*8..+7 of the 32x1024 candidate GEMM
// Weights live in smem (bf16 hi/lo) for all 512 steps. Activations are carried
// as bf16 hi/lo device globals written by the previous phase's epilogue.
extern __shared__ __align__(16) char dsraw[];
__global__ void __launch_bounds__(256, 1)
scan_persistent(const float* __restrict__ weight,
                const float* __restrict__ G,
                float* __restrict__ U,
                float* __restrict__ hcur,
                float* __restrict__ HT)
{
    __nv_bfloat16* ws1_hi = (__nv_bfloat16*)dsraw;            // 16 x WSP
    __nv_bfloat16* ws1_lo = ws1_hi + 16 * WSP;
    __nv_bfloat16* ws2_hi = ws1_lo + 16 * WSP;                // 8 x WSP
    __nv_bfloat16* ws2_lo = ws2_hi + 8 * WSP;
    __nv_bfloat16* hs_hi  = ws2_lo + 8 * WSP;                 // 32 x HSP
    __nv_bfloat16* hs_lo  = hs_hi + 32 * HSP;
    float* red = (float*)(hs_lo + 32 * HSP);                  // 8*512 floats

    const int tid  = threadIdx.x;
    const int bx   = blockIdx.x;
    const int lane = tid & 31, warp = tid >> 5;
    const int g = lane >> 2, tig = lane & 3;

    // ---- load + split weight slices into smem (once) ----
    for (int i = 0; i < 64; i++) {
        int idx = tid + i * 256;             // 16384: c=idx&15, k=idx>>4
        int c = idx & 15, k = idx >> 4;
        float v = weight[(long)(1024 + k) * WLD + bx * 16 + c];
        __nv_bfloat16 h = __float2bfloat16(v);
        ws1_hi[c * WSP + k] = h;
        ws1_lo[c * WSP + k] = __float2bfloat16(v - __bfloat162float(h));
    }
    for (int i = 0; i < 32; i++) {
        int idx = tid + i * 256;             // 8192: c=idx&7, k=idx>>3
        int c = idx & 7, k = idx >> 3;
        float v = weight[(long)(1024 + k) * WLD + 2048 + bx * 8 + c];
        __nv_bfloat16 h = __float2bfloat16(v);
        ws2_hi[c * WSP + k] = h;
        ws2_lo[c * WSP + k] = __float2bfloat16(v - __bfloat162float(h));
    }
    __syncthreads();

    // phase1 output pair for this thread
    const int o1 = tid * 2;
    const int r1 = o1 >> 4, c1 = o1 & 15;
    const int col1 = bx * 16 + c1;
    // phase2 output for this thread
    const int r2 = tid >> 3, c2 = tid & 7;
    const int d2 = bx * 8 + c2;

    unsigned tgt = NB;

    for (int t = 0; t < TT; t++) {
        // ---- prefetch G rows + hcur values for epilogues ----
        float2 g1 = *(const float2*)&G[((long)r1 * TT + t) * 3072 + col1];
        float2 hv1 = make_float2(0.f, 0.f);
        if (col1 >= 1024)
            hv1 = *(const float2*)&hcur[r1 * 1024 + (col1 - 1024)];
        float g2 = G[((long)r2 * TT + t) * 3072 + 2048 + d2];
        float hp = hcur[r2 * 1024 + d2];

        // ================= phase 1: 32x16 = h(32x1024) @ Whtg slice =========
        float acc[2][2][4];
#pragma unroll
        for (int i = 0; i < 2; i++)
#pragma unroll
            for (int j = 0; j < 2; j++)
#pragma unroll
                for (int e = 0; e < 4; e++) acc[i][j][e] = 0.f;

        for (int ch = 0; ch < 2; ch++) {
            const int kc = ch * 512;
            __syncthreads();
            // stage 32x512 bf16 hi/lo (vectorized 16B)
#pragma unroll
            for (int i = 0; i < 8; i++) {
                int idx = tid + i * 256;              // 0..2047
                int r = idx >> 6, kv = (idx & 63) * 8;
                *(uint4*)&hs_hi[r * HSP + kv] = *(const uint4*)&g_h_hi[r * 1024 + kc + kv];
                *(uint4*)&hs_lo[r * HSP + kv] = *(const uint4*)&g_h_lo[r * 1024 + kc + kv];
            }
            __syncthreads();

#pragma unroll
            for (int q = 0; q < 4; q++) {
                int kb = (warp + 8 * q) * 16;         // chunk-local k base
                uint32_t ah[2][4], al[2][4], bh[2][2], bl[2][2];
#pragma unroll
                for (int i = 0; i < 2; i++) {
                    int r = i * 16 + g;
                    int c = kb + tig * 2;
                    ah[i][0] = *(const uint32_t*)&hs_hi[r * HSP + c];
                    ah[i][1] = *(const uint32_t*)&hs_hi[(r + 8) * HSP + c];
                    ah[i][2] = *(const uint32_t*)&hs_hi[r * HSP + c + 8];
                    ah[i][3] = *(const uint32_t*)&hs_hi[(r + 8) * HSP + c + 8];
                    al[i][0] = *(const uint32_t*)&hs_lo[r * HSP + c];
                    al[i][1] = *(const uint32_t*)&hs_lo[(r + 8) * HSP + c];
                    al[i][2] = *(const uint32_t*)&hs_lo[r * HSP + c + 8];
                    al[i][3] = *(const uint32_t*)&hs_lo[(r + 8) * HSP + c + 8];
                }
#pragma unroll
                for (int j = 0; j < 2; j++) {
                    int n = j * 8 + g;
                    int k = kc + kb + tig * 2;
                    bh[j][0] = *(const uint32_t*)&ws1_hi[n * WSP + k];
                    bh[j][1] = *(const uint32_t*)&ws1_hi[n * WSP + k + 8];
                    bl[j][0] = *(const uint32_t*)&ws1_lo[n * WSP + k];
                    bl[j][1] = *(const uint32_t*)&ws1_lo[n * WSP + k + 8];
                }
#pragma unroll
                for (int i = 0; i < 2; i++)
#pragma unroll
                    for (int j = 0; j < 2; j++) {
                        mma16816(acc[i][j], ah[i], bh[j]);
                        mma16816(acc[i][j], ah[i], bl[j]);
                        mma16816(acc[i][j], al[i], bh[j]);
                    }
            }
        }
        // cross-warp reduce
        __syncthreads();
#pragma unroll
        for (int i = 0; i < 2; i++)
#pragma unroll
            for (int j = 0; j < 2; j++) {
                int r = i * 16 + g, c = j * 8 + tig * 2;
                red[warp * 512 + r * 16 + c]           = acc[i][j][0];
                red[warp * 512 + r * 16 + c + 1]       = acc[i][j][1];
                red[warp * 512 + (r + 8) * 16 + c]     = acc[i][j][2];
                red[warp * 512 + (r + 8) * 16 + c + 1] = acc[i][j][3];
            }
        __syncthreads();
        {
            float v0 = g1.x, v1 = g1.y;
#pragma unroll
            for (int w = 0; w < 8; w++) {
                float2 p = *(const float2*)&red[w * 512 + o1];
                v0 += p.x; v1 += p.y;
            }
            float s0 = 1.f / (1.f + expf(-v0));
            float s1 = 1.f / (1.f + expf(-v1));
            if (col1 < 1024) {
                *(float2*)&U[r1 * 1024 + col1] = make_float2(s0, s1);
            } else {
                int d = col1 - 1024;
                float rh0 = s0 * hv1.x, rh1 = s1 * hv1.y;
                __nv_bfloat16 h0 = __float2bfloat16(rh0);
                __nv_bfloat16 h1 = __float2bfloat16(rh1);
                __nv_bfloat162 hip; hip.x = h0; hip.y = h1;
                __nv_bfloat162 lop;
                lop.x = __float2bfloat16(rh0 - __bfloat162float(h0));
                lop.y = __float2bfloat16(rh1 - __bfloat162float(h1));
                *(__nv_bfloat162*)&g_rh_hi[r1 * 1024 + d] = hip;
                *(__nv_bfloat162*)&g_rh_lo[r1 * 1024 + d] = lop;
            }
        }

        gridbar(tgt); tgt += NB;

        // ================= phase 2: 32x8 = RH(32x1024) @ Whtc slice =========
        float uu = U[r2 * 1024 + d2];   // after barrier A

        float acc2[2][4];
#pragma unroll
        for (int i = 0; i < 2; i++)
#pragma unroll
            for (int e = 0; e < 4; e++) acc2[i][e] = 0.f;

        for (int ch = 0; ch < 2; ch++) {
            const int kc = ch * 512;
            __syncthreads();
#pragma unroll
            for (int i = 0; i < 8; i++) {
                int idx = tid + i * 256;
                int r = idx >> 6, kv = (idx & 63) * 8;
                *(uint4*)&hs_hi[r * HSP + kv] = *(const uint4*)&g_rh_hi[r * 1024 + kc + kv];
                *(uint4*)&hs_lo[r * HSP + kv] = *(const uint4*)&g_rh_lo[r * 1024 + kc + kv];
            }
            __syncthreads();

#pragma unroll
            for (int q = 0; q < 4; q++) {
                int kb = (warp + 8 * q) * 16;
                uint32_t ah[2][4], al[2][4], bh[2], bl[2];
#pragma unroll
                for (int i = 0; i < 2; i++) {
                    int r = i * 16 + g;
                    int c = kb + tig * 2;
                    ah[i][0] = *(const uint32_t*)&hs_hi[r * HSP + c];
                    ah[i][1] = *(const uint32_t*)&hs_hi[(r + 8) * HSP + c];
                    ah[i][2] = *(const uint32_t*)&hs_hi[r * HSP + c + 8];
                    ah[i][3] = *(const uint32_t*)&hs_hi[(r + 8) * HSP + c + 8];
                    al[i][0] = *(const uint32_t*)&hs_lo[r * HSP + c];
                    al[i][1] = *(const uint32_t*)&hs_lo[(r + 8) * HSP + c];
                    al[i][2] = *(const uint32_t*)&hs_lo[r * HSP + c + 8];
                    al[i][3] = *(const uint32_t*)&hs_lo[(r + 8) * HSP + c + 8];
                }
                {
                    int n = g;
                    int k = kc + kb + tig * 2;
                    bh[0] = *(const uint32_t*)&ws2_hi[n * WSP + k];
                    bh[1] = *(const uint32_t*)&ws2_hi[n * WSP + k + 8];
                    bl[0] = *(const uint32_t*)&ws2_lo[n * WSP + k];
                    bl[1] = *(const uint32_t*)&ws2_lo[n * WSP + k + 8];
                }
#pragma unroll
                for (int i = 0; i < 2; i++) {
                    mma16816(acc2[i], ah[i], bh);
                    mma16816(acc2[i], ah[i], bl);
                    mma16816(acc2[i], al[i], bh);
                }
            }
        }
        __syncthreads();
#pragma unroll
        for (int i = 0; i < 2; i++) {
            int r = i * 16 + g, c = tig * 2;
            red[warp * 256 + r * 8 + c]           = acc2[i][0];
            red[warp * 256 + r * 8 + c + 1]       = acc2[i][1];
            red[warp * 256 + (r + 8) * 8 + c]     = acc2[i][2];
            red[warp * 256 + (r + 8) * 8 + c + 1] = acc2[i][3];
        }
        __syncthreads();
        {
            float v = g2;
#pragma unroll
            for (int w = 0; w < 8; w++) v += red[w * 256 + tid];
            float hc = tanhf(v);
            float hn = hp + uu * (hc - hp);
            hcur[r2 * 1024 + d2] = hn;
            HT[((long)r2 * TT + t) * 1024 + d2] = hn;
            __nv_bfloat16 hi = __float2bfloat16(hn);
            g_h_hi[r2 * 1024 + d2] = hi;
            g_h_lo[r2 * 1024 + d2] = __float2bfloat16(hn - __bfloat162float(hi));
        }

        gridbar(tgt); tgt += NB;
    }
}

__global__ void copy_last(const float* __restrict__ HT, float* __restrict__ out)
{
    int i = blockIdx.x * 256 + threadIdx.x;
    int n = i >> 10, c = i & 1023;
    out[i] = HT[((long)n * TT + (TT - 1)) * 1024 + c];
}

// ---------------- launch ------------------------------------------------------
#define SCAN_SMEM ((2*16*WSP + 2*8*WSP + 2*32*HSP) * 2 + 8*512*4)

extern "C" void kernel_launch(void* const* d_in, const int* in_sizes, int n_in,
                              void* d_out, int out_size)
{
    const float* x       = (const float*)d_in[0];
    const float* prev_ht = (const float*)d_in[1];
    const float* weight  = (const float*)d_in[2];
    const float* bias    = (const float*)d_in[3];
    float* out = (float*)d_out;

    float *G, *HT, *HC, *U, *UD, *RX;
    cudaGetSymbolAddress((void**)&G,  g_gates);
    cudaGetSymbolAddress((void**)&HT, g_HT);
    cudaGetSymbolAddress((void**)&HC, g_hcur);
    cudaGetSymbolAddress((void**)&U,  g_U);
    cudaGetSymbolAddress((void**)&UD, g_UD);
    cudaGetSymbolAddress((void**)&RX, g_RX);

    static int smem_set = 0;
    if (!smem_set) {
        cudaFuncSetAttribute(scan_persistent,
                             cudaFuncAttributeMaxDynamicSharedMemorySize,
                             SCAN_SMEM);
        smem_set = 1;
    }

    // gates = x @ Wxt + bt   (M=16384, Nc=3072, K=1024)
    mma_gemm<0><<<dim3(3072 / 128, MROWS / 128), 256>>>(
        x, nullptr, weight, bias, nullptr, G, nullptr, nullptr, 1024, 3072);

    // sequential scan: one persistent tensor-core kernel
    scan_init<<<128, 256>>>(prev_ht);
    scan_persistent<<<NB, 256, SCAN_SMEM>>>(weight, G, U, HC, HT);

    // F1: grd = sigmoid(bd[:2D] + x@Wxd[:,:2D] + ht@Whd[:,:2D]) -> UD, RX
    mma_gemm<1><<<dim3(2048 / 128, MROWS / 128), 256>>>(
        x, HT, weight + 3072, bias + 3072, x, UD, RX, nullptr, 2048, 2048);

    // F2: hcd = tanh(bd[2D:] + ht@Whd[:,2D:] + (rd*x)@Wxd[:,2D:]);
    //     h = x + ud*(hcd - x)
    mma_gemm<2><<<dim3(1024 / 128, MROWS / 128), 256>>>(
        RX, HT, weight + 5120, bias + 5120, x, out, nullptr, UD, 2048, 1024);

    // last_ht
    copy_last<<<128, 256>>>(HT, out + (size_t)MROWS * 1024);
}

// round 6
// speedup vs baseline: 2.7942x; 1.3306x over previous
#include <cuda_runtime.h>
#include <cuda_bf16.h>
#include <math.h>
#include <stdint.h>

// GridGRU: N=32, T=512, D=1024, H=1024
// inputs: x (N,T,D), prev_ht (N,H), weight (2048,6144), bias (6144)
// outputs: h (N,T,D) then last_ht (N,H), concatenated in d_out.

#define NN 32
#define TT 512
#define DD 1024
#define HH 1024
#define MROWS (NN*TT)        // 16384
#define WLD 6144
#define NB 128               // persistent scan blocks
#define GK 72                // gemm smem k stride (bf16) — 144B rows, conflict-free
#define WSP 1032             // scan weight smem k stride
#define HSP 264              // scan activation smem k stride

// ---------------- scratch (device globals) -----------------------------------
__device__ float g_gates[(size_t)MROWS * 3072];        // 192 MB
__device__ float g_hcur[NN * HH];
__device__ float g_U[NN * HH];
__device__ float g_UD[(size_t)MROWS * DD];             // 64 MB
__device__ __nv_bfloat16 g_Wt_hi[(size_t)6144 * 2048]; // transposed [col][k]
__device__ __nv_bfloat16 g_Wt_lo[(size_t)6144 * 2048];
__device__ __nv_bfloat16 g_X_hi[(size_t)MROWS * DD], g_X_lo[(size_t)MROWS * DD];
__device__ __nv_bfloat16 g_HT_hi[(size_t)MROWS * HH], g_HT_lo[(size_t)MROWS * HH];
__device__ __nv_bfloat16 g_RX_hi[(size_t)MROWS * DD], g_RX_lo[(size_t)MROWS * DD];
__device__ __nv_bfloat16 g_h_hi[NN * HH], g_h_lo[NN * HH];
__device__ __nv_bfloat16 g_rh_hi[NN * HH], g_rh_lo[NN * HH];
__device__ unsigned g_barcnt;

__device__ __forceinline__ void mma16816(float* c, const uint32_t* a, const uint32_t* b)
{
    asm volatile(
        "mma.sync.aligned.m16n8k16.row.col.f32.bf16.bf16.f32 "
        "{%0,%1,%2,%3}, {%4,%5,%6,%7}, {%8,%9}, {%0,%1,%2,%3};\n"
        : "+f"(c[0]), "+f"(c[1]), "+f"(c[2]), "+f"(c[3])
        : "r"(a[0]), "r"(a[1]), "r"(a[2]), "r"(a[3]), "r"(b[0]), "r"(b[1]));
}

// ---------------- prep: split x to bf16 hi/lo --------------------------------
__global__ void conv_x_kernel(const float* __restrict__ x)
{
    long i = ((long)blockIdx.x * 256 + threadIdx.x) * 8;
    float4 v0 = *(const float4*)(x + i);
    float4 v1 = *(const float4*)(x + i + 4);
    float v[8] = {v0.x, v0.y, v0.z, v0.w, v1.x, v1.y, v1.z, v1.w};
    __align__(16) __nv_bfloat16 hb[8], lb[8];
#pragma unroll
    for (int e = 0; e < 8; e++) {
        __nv_bfloat16 h = __float2bfloat16(v[e]);
        hb[e] = h;
        lb[e] = __float2bfloat16(v[e] - __bfloat162float(h));
    }
    *(uint4*)&g_X_hi[i] = *(uint4*)hb;
    *(uint4*)&g_X_lo[i] = *(uint4*)lb;
}

// ---------------- prep: split + transpose weight to [col][k] bf16 ------------
__global__ void conv_w_kernel(const float* __restrict__ W)
{
    __shared__ float ws[64][65];
    const int k0 = blockIdx.x * 64, c0 = blockIdx.y * 64;
    const int tid = threadIdx.x;
#pragma unroll
    for (int s = 0; s < 4; s++) {
        int f = tid + s * 256;
        int kr = f >> 4, cc = (f & 15) * 4;
        float4 v = *(const float4*)(W + (long)(k0 + kr) * WLD + c0 + cc);
        ws[kr][cc] = v.x; ws[kr][cc + 1] = v.y; ws[kr][cc + 2] = v.z; ws[kr][cc + 3] = v.w;
    }
    __syncthreads();
    const int col = tid & 63, kq = tid >> 6;
    __align__(16) __nv_bfloat16 hb[16], lb[16];
#pragma unroll
    for (int j = 0; j < 16; j++) {
        float v = ws[kq * 16 + j][col];
        __nv_bfloat16 h = __float2bfloat16(v);
        hb[j] = h;
        lb[j] = __float2bfloat16(v - __bfloat162float(h));
    }
    long dst = (long)(c0 + col) * 2048 + k0 + kq * 16;
    ((uint4*)&g_Wt_hi[dst])[0] = ((uint4*)hb)[0];
    ((uint4*)&g_Wt_hi[dst])[1] = ((uint4*)hb)[1];
    ((uint4*)&g_Wt_lo[dst])[0] = ((uint4*)lb)[0];
    ((uint4*)&g_Wt_lo[dst])[1] = ((uint4*)lb)[1];
}

// ---------------- big GEMM: bf16 hi/lo inputs, double-buffered ---------------
// C = concatK(A0,A1) @ Bt^T + epilogue.  Bt is [col][2048] (k contiguous).
// EPI 0: gates -> out = acc + bias
// EPI 1: s = sigmoid(acc+bias); col<1024 ? out(UD)=s : RX_hi/lo = split(s*x)
// EPI 2: hc = tanh(acc+bias); out = x + UD*(hc-x)
template<int EPI>
__global__ void __launch_bounds__(256)
mma_gemm(const __nv_bfloat16* __restrict__ A0h, const __nv_bfloat16* __restrict__ A0l,
         const __nv_bfloat16* __restrict__ A1h, const __nv_bfloat16* __restrict__ A1l,
         const __nv_bfloat16* __restrict__ Bth, const __nv_bfloat16* __restrict__ Btl,
         const float* __restrict__ bias, const float* __restrict__ X,
         float* __restrict__ out, const float* __restrict__ UD,
         int K, int ldc)
{
    extern __shared__ __align__(16) char gsm[];
    __nv_bfloat16* As = (__nv_bfloat16*)gsm;        // [stage][hi/lo][128*GK]
    __nv_bfloat16* Bs = As + 2 * 2 * 128 * GK;

    const int tid = threadIdx.x, lane = tid & 31, warp = tid >> 5;
    const int warpM = warp & 1, warpN = warp >> 1;
    const int g = lane >> 2, tig = lane & 3;
    const int row0 = blockIdx.y * 128, col0 = blockIdx.x * 128;
    const int rA = warpM * 64, cB = warpN * 32;
    const int ar0 = tid >> 2,          aq0 = (tid & 3) * 8;
    const int ar1 = (tid + 256) >> 2,  aq1 = (tid & 3) * 8;

    float acc[4][4][4];
#pragma unroll
    for (int i = 0; i < 4; i++)
#pragma unroll
        for (int j = 0; j < 4; j++)
#pragma unroll
            for (int e = 0; e < 4; e++) acc[i][j][e] = 0.f;

    uint4 ra[2][2], rb[2][2];

    auto LDG = [&](int k0) {
        {
            int kk = k0 + aq0;
            const __nv_bfloat16 *ph, *pl; long off;
            if (kk < 1024) { ph = A0h; pl = A0l; off = (long)(row0 + ar0) * 1024 + kk; }
            else           { ph = A1h; pl = A1l; off = (long)(row0 + ar0) * 1024 + kk - 1024; }
            ra[0][0] = *(const uint4*)(ph + off); ra[0][1] = *(const uint4*)(pl + off);
        }
        {
            int kk = k0 + aq1;
            const __nv_bfloat16 *ph, *pl; long off;
            if (kk < 1024) { ph = A0h; pl = A0l; off = (long)(row0 + ar1) * 1024 + kk; }
            else           { ph = A1h; pl = A1l; off = (long)(row0 + ar1) * 1024 + kk - 1024; }
            ra[1][0] = *(const uint4*)(ph + off); ra[1][1] = *(const uint4*)(pl + off);
        }
        {
            long off = (long)(col0 + ar0) * 2048 + k0 + aq0;
            rb[0][0] = *(const uint4*)(Bth + off); rb[0][1] = *(const uint4*)(Btl + off);
        }
        {
            long off = (long)(col0 + ar1) * 2048 + k0 + aq1;
            rb[1][0] = *(const uint4*)(Bth + off); rb[1][1] = *(const uint4*)(Btl + off);
        }
    };
    auto STS = [&](int st) {
        *(uint4*)&As[(st * 2 + 0) * 128 * GK + ar0 * GK + aq0] = ra[0][0];
        *(uint4*)&As[(st * 2 + 1) * 128 * GK + ar0 * GK + aq0] = ra[0][1];
        *(uint4*)&As[(st * 2 + 0) * 128 * GK + ar1 * GK + aq1] = ra[1][0];
        *(uint4*)&As[(st * 2 + 1) * 128 * GK + ar1 * GK + aq1] = ra[1][1];
        *(uint4*)&Bs[(st * 2 + 0) * 128 * GK + ar0 * GK + aq0] = rb[0][0];
        *(uint4*)&Bs[(st * 2 + 1) * 128 * GK + ar0 * GK + aq0] = rb[0][1];
        *(uint4*)&Bs[(st * 2 + 0) * 128 * GK + ar1 * GK + aq1] = rb[1][0];
        *(uint4*)&Bs[(st * 2 + 1) * 128 * GK + ar1 * GK + aq1] = rb[1][1];
    };

    const int KT = K / 32;
    LDG(0); STS(0);
    __syncthreads();

    for (int kt = 0; kt < KT; kt++) {
        const int st = kt & 1;
        if (kt + 1 < KT) LDG((kt + 1) * 32);

        const __nv_bfloat16* Ah = As + (st * 2 + 0) * 128 * GK;
        const __nv_bfloat16* Al = As + (st * 2 + 1) * 128 * GK;
        const __nv_bfloat16* Bh = Bs + (st * 2 + 0) * 128 * GK;
        const __nv_bfloat16* Bl = Bs + (st * 2 + 1) * 128 * GK;

#pragma unroll
        for (int kk = 0; kk < 32; kk += 16) {
            uint32_t ah[4][4], al[4][4], bh[4][2], bl[4][2];
#pragma unroll
            for (int i = 0; i < 4; i++) {
                int r = rA + i * 16 + g, c = kk + tig * 2;
                ah[i][0] = *(const uint32_t*)&Ah[r * GK + c];
                ah[i][1] = *(const uint32_t*)&Ah[(r + 8) * GK + c];
                ah[i][2] = *(const uint32_t*)&Ah[r * GK + c + 8];
                ah[i][3] = *(const uint32_t*)&Ah[(r + 8) * GK + c + 8];
                al[i][0] = *(const uint32_t*)&Al[r * GK + c];
                al[i][1] = *(const uint32_t*)&Al[(r + 8) * GK + c];
                al[i][2] = *(const uint32_t*)&Al[r * GK + c + 8];
                al[i][3] = *(const uint32_t*)&Al[(r + 8) * GK + c + 8];
            }
#pragma unroll
            for (int j = 0; j < 4; j++) {
                int n = cB + j * 8 + g, c = kk + tig * 2;
                bh[j][0] = *(const uint32_t*)&Bh[n * GK + c];
                bh[j][1] = *(const uint32_t*)&Bh[n * GK + c + 8];
                bl[j][0] = *(const uint32_t*)&Bl[n * GK + c];
                bl[j][1] = *(const uint32_t*)&Bl[n * GK + c + 8];
            }
#pragma unroll
            for (int i = 0; i < 4; i++)
#pragma unroll
                for (int j = 0; j < 4; j++) {
                    mma16816(acc[i][j], ah[i], bh[j]);
                    mma16816(acc[i][j], ah[i], bl[j]);
                    mma16816(acc[i][j], al[i], bh[j]);
                }
        }
        if (kt + 1 < KT) STS(st ^ 1);
        __syncthreads();
    }

    auto epi2 = [&](long row, int col, float v0, float v1) {
        v0 += bias[col]; v1 += bias[col + 1];
        if (EPI == 0) {
            out[row * (long)ldc + col]     = v0;
            out[row * (long)ldc + col + 1] = v1;
        } else if (EPI == 1) {
            float s0 = 1.f / (1.f + __expf(-v0));
            float s1 = 1.f / (1.f + __expf(-v1));
            if (col < 1024) {
                out[row * 1024 + col]     = s0;
                out[row * 1024 + col + 1] = s1;
            } else {
                int d = col - 1024;
                float rx0 = s0 * X[row * 1024 + d];
                float rx1 = s1 * X[row * 1024 + d + 1];
                __nv_bfloat16 h0 = __float2bfloat16(rx0);
                __nv_bfloat16 h1 = __float2bfloat16(rx1);
                __nv_bfloat162 hp; hp.x = h0; hp.y = h1;
                __nv_bfloat162 lp;
                lp.x = __float2bfloat16(rx0 - __bfloat162float(h0));
                lp.y = __float2bfloat16(rx1 - __bfloat162float(h1));
                *(__nv_bfloat162*)&g_RX_hi[row * 1024 + d] = hp;
                *(__nv_bfloat162*)&g_RX_lo[row * 1024 + d] = lp;
            }
        } else {
            float hc0 = tanhf(v0), hc1 = tanhf(v1);
            float x0 = X[row * 1024 + col], x1 = X[row * 1024 + col + 1];
            out[row * 1024 + col]     = x0 + UD[row * 1024 + col] * (hc0 - x0);
            out[row * 1024 + col + 1] = x1 + UD[row * 1024 + col + 1] * (hc1 - x1);
        }
    };

#pragma unroll
    for (int i = 0; i < 4; i++) {
        long r = row0 + rA + i * 16 + g;
#pragma unroll
        for (int j = 0; j < 4; j++) {
            int cc = col0 + cB + j * 8 + tig * 2;
            epi2(r,     cc, acc[i][j][0], acc[i][j][1]);
            epi2(r + 8, cc, acc[i][j][2], acc[i][j][3]);
        }
    }
}

// ---------------- scan init --------------------------------------------------
__global__ void scan_init(const float* __restrict__ prev_ht)
{
    int i = blockIdx.x * 256 + threadIdx.x;   // 32768
    if (i == 0) g_barcnt = 0;
    float v = prev_ht[i];
    g_hcur[i] = v;
    __nv_bfloat16 hi = __float2bfloat16(v);
    g_h_hi[i] = hi;
    g_h_lo[i] = __float2bfloat16(v - __bfloat162float(hi));
}

__device__ __forceinline__ void gridbar(unsigned target)
{
    __syncthreads();
    if (threadIdx.x == 0) {
        asm volatile("red.release.gpu.global.add.u32 [%0], 1;"
                     :: "l"(&g_barcnt) : "memory");
        unsigned v;
        do {
            asm volatile("ld.acquire.gpu.global.u32 %0, [%1];"
                         : "=r"(v) : "l"(&g_barcnt) : "memory");
        } while (v < target);
    }
    __syncthreads();
}

// ---------------- persistent tensor-core scan (pipelined staging) ------------
extern __shared__ __align__(16) char dsraw[];
__global__ void __launch_bounds__(256, 1)
scan_persistent()
{
    __nv_bfloat16* ws1h = (__nv_bfloat16*)dsraw;
    __nv_bfloat16* ws1l = ws1h + 16 * WSP;
    __nv_bfloat16* ws2h = ws1l + 16 * WSP;
    __nv_bfloat16* ws2l = ws2h + 8 * WSP;
    __nv_bfloat16* hsh0 = ws2l + 8 * WSP;
    __nv_bfloat16* hsl0 = hsh0 + 32 * HSP;
    __nv_bfloat16* hsh1 = hsl0 + 32 * HSP;
    __nv_bfloat16* hsl1 = hsh1 + 32 * HSP;
    float* red = (float*)(hsl1 + 32 * HSP);

    const int tid = threadIdx.x, bx = blockIdx.x;
    const int lane = tid & 31, warp = tid >> 5;
    const int g = lane >> 2, tig = lane & 3;

    // ---- weight slices from pre-split transposed W (once) ----
#pragma unroll
    for (int s = 0; s < 8; s++) {
        int f = tid + s * 256;                 // 0..2047
        int c = f >> 7, q = (f & 127) * 8;
        *(uint4*)(ws1h + c * WSP + q) = *(const uint4*)&g_Wt_hi[(long)(bx * 16 + c) * 2048 + 1024 + q];
        *(uint4*)(ws1l + c * WSP + q) = *(const uint4*)&g_Wt_lo[(long)(bx * 16 + c) * 2048 + 1024 + q];
    }
#pragma unroll
    for (int s = 0; s < 4; s++) {
        int f = tid + s * 256;                 // 0..1023
        int c = f >> 7, q = (f & 127) * 8;
        *(uint4*)(ws2h + c * WSP + q) = *(const uint4*)&g_Wt_hi[(long)(2048 + bx * 8 + c) * 2048 + 1024 + q];
        *(uint4*)(ws2l + c * WSP + q) = *(const uint4*)&g_Wt_lo[(long)(2048 + bx * 8 + c) * 2048 + 1024 + q];
    }
    __syncthreads();

    const int o1 = tid * 2;
    const int r1 = o1 >> 4, c1 = o1 & 15;
    const int col1 = bx * 16 + c1;
    const int r2 = tid >> 3, c2 = tid & 7;
    const int d2 = bx * 8 + c2;

    unsigned tgt = NB;
    uint4 sh[4], sl[4];

    for (int t = 0; t < TT; t++) {
        float2 g1 = *(const float2*)&g_gates[((long)r1 * TT + t) * 3072 + col1];
        float2 hv1 = make_float2(0.f, 0.f);
        if (col1 >= 1024)
            hv1 = *(const float2*)&g_hcur[r1 * 1024 + (col1 - 1024)];
        float gg2 = g_gates[((long)r2 * TT + t) * 3072 + 2048 + d2];
        float hp = g_hcur[r2 * 1024 + d2];

        // ================= phase 1 =================
        float acc[2][2][4];
#pragma unroll
        for (int i = 0; i < 2; i++)
#pragma unroll
            for (int j = 0; j < 2; j++)
#pragma unroll
                for (int e = 0; e < 4; e++) acc[i][j][e] = 0.f;

        // stage chunk0
#pragma unroll
        for (int s = 0; s < 4; s++) {
            int f = tid + s * 256; int r = f >> 5, q = (f & 31) * 8;
            sh[s] = *(const uint4*)&g_h_hi[r * 1024 + q];
            sl[s] = *(const uint4*)&g_h_lo[r * 1024 + q];
        }
#pragma unroll
        for (int s = 0; s < 4; s++) {
            int f = tid + s * 256; int r = f >> 5, q = (f & 31) * 8;
            *(uint4*)&hsh0[r * HSP + q] = sh[s];
            *(uint4*)&hsl0[r * HSP + q] = sl[s];
        }

        for (int ch = 0; ch < 4; ch++) {
            __syncthreads();
            if (ch < 3) {
                int kc = (ch + 1) * 256;
#pragma unroll
                for (int s = 0; s < 4; s++) {
                    int f = tid + s * 256; int r = f >> 5, q = (f & 31) * 8;
                    sh[s] = *(const uint4*)&g_h_hi[r * 1024 + kc + q];
                    sl[s] = *(const uint4*)&g_h_lo[r * 1024 + kc + q];
                }
            }
            const __nv_bfloat16* Ah = (ch & 1) ? hsh1 : hsh0;
            const __nv_bfloat16* Al = (ch & 1) ? hsl1 : hsl0;
#pragma unroll
            for (int kk = 0; kk < 32; kk += 16) {
                int kl = warp * 32 + kk + tig * 2;   // chunk-local
                int kg = ch * 256 + kl;              // global k
                uint32_t ah[2][4], al[2][4], bh[2][2], bl[2][2];
#pragma unroll
                for (int i = 0; i < 2; i++) {
                    int r = i * 16 + g;
                    ah[i][0] = *(const uint32_t*)&Ah[r * HSP + kl];
                    ah[i][1] = *(const uint32_t*)&Ah[(r + 8) * HSP + kl];
                    ah[i][2] = *(const uint32_t*)&Ah[r * HSP + kl + 8];
                    ah[i][3] = *(const uint32_t*)&Ah[(r + 8) * HSP + kl + 8];
                    al[i][0] = *(const uint32_t*)&Al[r * HSP + kl];
                    al[i][1] = *(const uint32_t*)&Al[(r + 8) * HSP + kl];
                    al[i][2] = *(const uint32_t*)&Al[r * HSP + kl + 8];
                    al[i][3] = *(const uint32_t*)&Al[(r + 8) * HSP + kl + 8];
                }
#pragma unroll
                for (int j = 0; j < 2; j++) {
                    int n = j * 8 + g;
                    bh[j][0] = *(const uint32_t*)&ws1h[n * WSP + kg];
                    bh[j][1] = *(const uint32_t*)&ws1h[n * WSP + kg + 8];
                    bl[j][0] = *(const uint32_t*)&ws1l[n * WSP + kg];
                    bl[j][1] = *(const uint32_t*)&ws1l[n * WSP + kg + 8];
                }
#pragma unroll
                for (int i = 0; i < 2; i++)
#pragma unroll
                    for (int j = 0; j < 2; j++) {
                        mma16816(acc[i][j], ah[i], bh[j]);
                        mma16816(acc[i][j], ah[i], bl[j]);
                        mma16816(acc[i][j], al[i], bh[j]);
                    }
            }
            if (ch < 3) {
                __nv_bfloat16* dh = (ch & 1) ? hsh0 : hsh1;
                __nv_bfloat16* dl = (ch & 1) ? hsl0 : hsl1;
#pragma unroll
                for (int s = 0; s < 4; s++) {
                    int f = tid + s * 256; int r = f >> 5, q = (f & 31) * 8;
                    *(uint4*)&dh[r * HSP + q] = sh[s];
                    *(uint4*)&dl[r * HSP + q] = sl[s];
                }
            }
        }
        __syncthreads();
#pragma unroll
        for (int i = 0; i < 2; i++)
#pragma unroll
            for (int j = 0; j < 2; j++) {
                int r = i * 16 + g, c = j * 8 + tig * 2;
                red[warp * 512 + r * 16 + c]           = acc[i][j][0];
                red[warp * 512 + r * 16 + c + 1]       = acc[i][j][1];
                red[warp * 512 + (r + 8) * 16 + c]     = acc[i][j][2];
                red[warp * 512 + (r + 8) * 16 + c + 1] = acc[i][j][3];
            }
        __syncthreads();
        {
            float v0 = g1.x, v1 = g1.y;
#pragma unroll
            for (int w = 0; w < 8; w++) {
                float2 p = *(const float2*)&red[w * 512 + o1];
                v0 += p.x; v1 += p.y;
            }
            float s0 = 1.f / (1.f + __expf(-v0));
            float s1 = 1.f / (1.f + __expf(-v1));
            if (col1 < 1024) {
                *(float2*)&g_U[r1 * 1024 + col1] = make_float2(s0, s1);
            } else {
                int d = col1 - 1024;
                float rh0 = s0 * hv1.x, rh1 = s1 * hv1.y;
                __nv_bfloat16 h0 = __float2bfloat16(rh0);
                __nv_bfloat16 h1 = __float2bfloat16(rh1);
                __nv_bfloat162 hip; hip.x = h0; hip.y = h1;
                __nv_bfloat162 lop;
                lop.x = __float2bfloat16(rh0 - __bfloat162float(h0));
                lop.y = __float2bfloat16(rh1 - __bfloat162float(h1));
                *(__nv_bfloat162*)&g_rh_hi[r1 * 1024 + d] = hip;
                *(__nv_bfloat162*)&g_rh_lo[r1 * 1024 + d] = lop;
            }
        }

        gridbar(tgt); tgt += NB;

        // ================= phase 2 =================
        float uu = g_U[r2 * 1024 + d2];

        float acc2[2][4];
#pragma unroll
        for (int i = 0; i < 2; i++)
#pragma unroll
            for (int e = 0; e < 4; e++) acc2[i][e] = 0.f;

#pragma unroll
        for (int s = 0; s < 4; s++) {
            int f = tid + s * 256; int r = f >> 5, q = (f & 31) * 8;
            sh[s] = *(const uint4*)&g_rh_hi[r * 1024 + q];
            sl[s] = *(const uint4*)&g_rh_lo[r * 1024 + q];
        }
#pragma unroll
        for (int s = 0; s < 4; s++) {
            int f = tid + s * 256; int r = f >> 5, q = (f & 31) * 8;
            *(uint4*)&hsh0[r * HSP + q] = sh[s];
            *(uint4*)&hsl0[r * HSP + q] = sl[s];
        }

        for (int ch = 0; ch < 4; ch++) {
            __syncthreads();
            if (ch < 3) {
                int kc = (ch + 1) * 256;
#pragma unroll
                for (int s = 0; s < 4; s++) {
                    int f = tid + s * 256; int r = f >> 5, q = (f & 31) * 8;
                    sh[s] = *(const uint4*)&g_rh_hi[r * 1024 + kc + q];
                    sl[s] = *(const uint4*)&g_rh_lo[r * 1024 + kc + q];
                }
            }
            const __nv_bfloat16* Ah = (ch & 1) ? hsh1 : hsh0;
            const __nv_bfloat16* Al = (ch & 1) ? hsl1 : hsl0;
#pragma unroll
            for (int kk = 0; kk < 32; kk += 16) {
                int kl = warp * 32 + kk + tig * 2;
                int kg = ch * 256 + kl;
                uint32_t ah[2][4], al[2][4], bh[2], bl[2];
#pragma unroll
                for (int i = 0; i < 2; i++) {
                    int r = i * 16 + g;
                    ah[i][0] = *(const uint32_t*)&Ah[r * HSP + kl];
                    ah[i][1] = *(const uint32_t*)&Ah[(r + 8) * HSP + kl];
                    ah[i][2] = *(const uint32_t*)&Ah[r * HSP + kl + 8];
                    ah[i][3] = *(const uint32_t*)&Ah[(r + 8) * HSP + kl + 8];
                    al[i][0] = *(const uint32_t*)&Al[r * HSP + kl];
                    al[i][1] = *(const uint32_t*)&Al[(r + 8) * HSP + kl];
                    al[i][2] = *(const uint32_t*)&Al[r * HSP + kl + 8];
                    al[i][3] = *(const uint32_t*)&Al[(r + 8) * HSP + kl + 8];
                }
                {
                    int n = g;
                    bh[0] = *(const uint32_t*)&ws2h[n * WSP + kg];
                    bh[1] = *(const uint32_t*)&ws2h[n * WSP + kg + 8];
                    bl[0] = *(const uint32_t*)&ws2l[n * WSP + kg];
                    bl[1] = *(const uint32_t*)&ws2l[n * WSP + kg + 8];
                }
#pragma unroll
                for (int i = 0; i < 2; i++) {
                    mma16816(acc2[i], ah[i], bh);
                    mma16816(acc2[i], ah[i], bl);
                    mma16816(acc2[i], al[i], bh);
                }
            }
            if (ch < 3) {
                __nv_bfloat16* dh = (ch & 1) ? hsh0 : hsh1;
                __nv_bfloat16* dl = (ch & 1) ? hsl0 : hsl1;
#pragma unroll
                for (int s = 0; s < 4; s++) {
                    int f = tid + s * 256; int r = f >> 5, q = (f & 31) * 8;
                    *(uint4*)&dh[r * HSP + q] = sh[s];
                    *(uint4*)&dl[r * HSP + q] = sl[s];
                }
            }
        }
        __syncthreads();
#pragma unroll
        for (int i = 0; i < 2; i++) {
            int r = i * 16 + g, c = tig * 2;
            red[warp * 256 + r * 8 + c]           = acc2[i][0];
            red[warp * 256 + r * 8 + c + 1]       = acc2[i][1];
            red[warp * 256 + (r + 8) * 8 + c]     = acc2[i][2];
            red[warp * 256 + (r + 8) * 8 + c + 1] = acc2[i][3];
        }
        __syncthreads();
        {
            float v = gg2;
#pragma unroll
            for (int w = 0; w < 8; w++) v += red[w * 256 + tid];
            float hc = tanhf(v);
            float hn = hp + uu * (hc - hp);
            g_hcur[r2 * 1024 + d2] = hn;
            __nv_bfloat16 hi = __float2bfloat16(hn);
            __nv_bfloat16 lo = __float2bfloat16(hn - __bfloat162float(hi));
            g_h_hi[r2 * 1024 + d2] = hi;
            g_h_lo[r2 * 1024 + d2] = lo;
            long ho = ((long)r2 * TT + t) * 1024 + d2;
            g_HT_hi[ho] = hi;
            g_HT_lo[ho] = lo;
        }

        gridbar(tgt); tgt += NB;
    }
}

__global__ void copy_last(float* __restrict__ out)
{
    int i = blockIdx.x * 256 + threadIdx.x;   // 32768
    out[i] = g_hcur[i];
}

// ---------------- launch ------------------------------------------------------
#define SCAN_SMEM ((48*WSP + 4*32*HSP) * 2 + 8*512*4)
#define GEMM_SMEM (2 * 2 * 2 * 128 * GK * 2)

extern "C" void kernel_launch(void* const* d_in, const int* in_sizes, int n_in,
                              void* d_out, int out_size)
{
    const float* x       = (const float*)d_in[0];
    const float* prev_ht = (const float*)d_in[1];
    const float* weight  = (const float*)d_in[2];
    const float* bias    = (const float*)d_in[3];
    float* out = (float*)d_out;

    float *G, *UD;
    __nv_bfloat16 *Wth, *Wtl, *Xh, *Xl, *HTh, *HTl, *RXh, *RXl;
    cudaGetSymbolAddress((void**)&G,   g_gates);
    cudaGetSymbolAddress((void**)&UD,  g_UD);
    cudaGetSymbolAddress((void**)&Wth, g_Wt_hi);
    cudaGetSymbolAddress((void**)&Wtl, g_Wt_lo);
    cudaGetSymbolAddress((void**)&Xh,  g_X_hi);
    cudaGetSymbolAddress((void**)&Xl,  g_X_lo);
    cudaGetSymbolAddress((void**)&HTh, g_HT_hi);
    cudaGetSymbolAddress((void**)&HTl, g_HT_lo);
    cudaGetSymbolAddress((void**)&RXh, g_RX_hi);
    cudaGetSymbolAddress((void**)&RXl, g_RX_lo);

    static int attr_set = 0;
    if (!attr_set) {
        cudaFuncSetAttribute(scan_persistent,
                             cudaFuncAttributeMaxDynamicSharedMemorySize, SCAN_SMEM);
        cudaFuncSetAttribute(mma_gemm<0>,
                             cudaFuncAttributeMaxDynamicSharedMemorySize, GEMM_SMEM);
        cudaFuncSetAttribute(mma_gemm<1>,
                             cudaFuncAttributeMaxDynamicSharedMemorySize, GEMM_SMEM);
        cudaFuncSetAttribute(mma_gemm<2>,
                             cudaFuncAttributeMaxDynamicSharedMemorySize, GEMM_SMEM);
        attr_set = 1;
    }

    // prep: split W (transposed) and x into bf16 hi/lo
    conv_w_kernel<<<dim3(2048 / 64, 6144 / 64), 256>>>(weight);
    conv_x_kernel<<<MROWS * DD / 8 / 256, 256>>>(x);

    // gates = x @ Wxt + bt
    mma_gemm<0><<<dim3(3072 / 128, MROWS / 128), 256, GEMM_SMEM>>>(
        Xh, Xl, Xh, Xl, Wth, Wtl, bias, nullptr, G, nullptr, 1024, 3072);

    // scan
    scan_init<<<128, 256>>>(prev_ht);
    scan_persistent<<<NB, 256, SCAN_SMEM>>>();

    // F1: sigmoid(bd[:2D] + [x|ht] @ W[:,3072:5120]) -> UD, RX
    mma_gemm<1><<<dim3(2048 / 128, MROWS / 128), 256, GEMM_SMEM>>>(
        Xh, Xl, HTh, HTl, Wth + (size_t)3072 * 2048, Wtl + (size_t)3072 * 2048,
        bias + 3072, x, UD, nullptr, 2048, 2048);

    // F2: tanh(bd[2D:] + [rd*x|ht] @ W[:,5120:6144]); out = x + ud*(hc-x)
    mma_gemm<2><<<dim3(1024 / 128, MROWS / 128), 256, GEMM_SMEM>>>(
        RXh, RXl, HTh, HTl, Wth + (size_t)5120 * 2048, Wtl + (size_t)5120 * 2048,
        bias + 5120, x, out, UD, 2048, 1024);

    // last_ht
    copy_last<<<128, 256>>>(out + (size_t)MROWS * 1024);
}

// round 7
// speedup vs baseline: 3.0013x; 1.0741x over previous
#include <cuda_runtime.h>
#include <cuda_bf16.h>
#include <math.h>
#include <stdint.h>

// GridGRU: N=32, T=512, D=1024, H=1024
// inputs: x (N,T,D), prev_ht (N,H), weight (2048,6144), bias (6144)
// outputs: h (N,T,D) then last_ht (N,H), concatenated in d_out.

#define NN 32
#define TT 512
#define DD 1024
#define HH 1024
#define MROWS (NN*TT)        // 16384
#define WLD 6144
#define NB 128               // persistent scan blocks
#define GK2 40               // gemm smem k stride (bf16)
#define WSP 1032             // scan weight smem k stride
#define HSP 264              // scan activation smem k stride

// ---------------- scratch (device globals) -----------------------------------
__device__ float g_gates[(size_t)MROWS * 3072];        // 192 MB
__device__ float g_hcur[NN * HH];
__device__ float g_U[NN * HH];
__device__ float g_UD[(size_t)MROWS * DD];             // 64 MB
__device__ __nv_bfloat16 g_Wt_hi[(size_t)6144 * 2048]; // transposed [col][k]
__device__ __nv_bfloat16 g_Wt_lo[(size_t)6144 * 2048];
__device__ __nv_bfloat16 g_X_hi[(size_t)MROWS * DD], g_X_lo[(size_t)MROWS * DD];
__device__ __nv_bfloat16 g_HT_hi[(size_t)MROWS * HH], g_HT_lo[(size_t)MROWS * HH];
__device__ __nv_bfloat16 g_RX_hi[(size_t)MROWS * DD], g_RX_lo[(size_t)MROWS * DD];
__device__ __nv_bfloat16 g_h_hi[NN * HH], g_h_lo[NN * HH];
__device__ __nv_bfloat16 g_rh_hi[NN * HH], g_rh_lo[NN * HH];
__device__ unsigned g_barcnt;

__device__ __forceinline__ void mma16816(float* c, const uint32_t* a, const uint32_t* b)
{
    asm volatile(
        "mma.sync.aligned.m16n8k16.row.col.f32.bf16.bf16.f32 "
        "{%0,%1,%2,%3}, {%4,%5,%6,%7}, {%8,%9}, {%0,%1,%2,%3};\n"
        : "+f"(c[0]), "+f"(c[1]), "+f"(c[2]), "+f"(c[3])
        : "r"(a[0]), "r"(a[1]), "r"(a[2]), "r"(a[3]), "r"(b[0]), "r"(b[1]));
}

__device__ __forceinline__ void cpa16(void* smem, const void* g)
{
    uint32_t a = (uint32_t)__cvta_generic_to_shared(smem);
    asm volatile("cp.async.cg.shared.global [%0], [%1], 16;" :: "r"(a), "l"(g));
}
#define CPA_COMMIT asm volatile("cp.async.commit_group;" ::: "memory")
#define CPA_WAIT(n) asm volatile("cp.async.wait_group %0;" :: "n"(n) : "memory")

// ---------------- prep: split x to bf16 hi/lo --------------------------------
__global__ void conv_x_kernel(const float* __restrict__ x)
{
    long i = ((long)blockIdx.x * 256 + threadIdx.x) * 8;
    float4 v0 = *(const float4*)(x + i);
    float4 v1 = *(const float4*)(x + i + 4);
    float v[8] = {v0.x, v0.y, v0.z, v0.w, v1.x, v1.y, v1.z, v1.w};
    __align__(16) __nv_bfloat16 hb[8], lb[8];
#pragma unroll
    for (int e = 0; e < 8; e++) {
        __nv_bfloat16 h = __float2bfloat16(v[e]);
        hb[e] = h;
        lb[e] = __float2bfloat16(v[e] - __bfloat162float(h));
    }
    *(uint4*)&g_X_hi[i] = *(uint4*)hb;
    *(uint4*)&g_X_lo[i] = *(uint4*)lb;
}

// ---------------- prep: split + transpose weight to [col][k] bf16 ------------
__global__ void conv_w_kernel(const float* __restrict__ W)
{
    __shared__ float ws[64][65];
    const int k0 = blockIdx.x * 64, c0 = blockIdx.y * 64;
    const int tid = threadIdx.x;
#pragma unroll
    for (int s = 0; s < 4; s++) {
        int f = tid + s * 256;
        int kr = f >> 4, cc = (f & 15) * 4;
        float4 v = *(const float4*)(W + (long)(k0 + kr) * WLD + c0 + cc);
        ws[kr][cc] = v.x; ws[kr][cc + 1] = v.y; ws[kr][cc + 2] = v.z; ws[kr][cc + 3] = v.w;
    }
    __syncthreads();
    const int col = tid & 63, kq = tid >> 6;
    __align__(16) __nv_bfloat16 hb[16], lb[16];
#pragma unroll
    for (int j = 0; j < 16; j++) {
        float v = ws[kq * 16 + j][col];
        __nv_bfloat16 h = __float2bfloat16(v);
        hb[j] = h;
        lb[j] = __float2bfloat16(v - __bfloat162float(h));
    }
    long dst = (long)(c0 + col) * 2048 + k0 + kq * 16;
    ((uint4*)&g_Wt_hi[dst])[0] = ((uint4*)hb)[0];
    ((uint4*)&g_Wt_hi[dst])[1] = ((uint4*)hb)[1];
    ((uint4*)&g_Wt_lo[dst])[0] = ((uint4*)lb)[0];
    ((uint4*)&g_Wt_lo[dst])[1] = ((uint4*)lb)[1];
}

// ---------------- big GEMM: bf16 hi/lo, cp.async double-buffer ---------------
// EPI 0: gates -> out = acc + bias
// EPI 1: s = sigmoid(acc+bias); col<1024 ? out(UD)=s : RX_hi/lo = split(s*x)
// EPI 2: hc = tanh(acc+bias); out = x + UD*(hc-x)
template<int EPI>
__global__ void __launch_bounds__(256, 2)
mma_gemm(const __nv_bfloat16* __restrict__ A0h, const __nv_bfloat16* __restrict__ A0l,
         const __nv_bfloat16* __restrict__ A1h, const __nv_bfloat16* __restrict__ A1l,
         const __nv_bfloat16* __restrict__ Bth, const __nv_bfloat16* __restrict__ Btl,
         const float* __restrict__ bias, const float* __restrict__ X,
         float* __restrict__ out, const float* __restrict__ UD,
         int K, int ldc)
{
    extern __shared__ __align__(16) char gsm[];
    __nv_bfloat16* As = (__nv_bfloat16*)gsm;        // [stage][hi/lo][128*GK2]
    __nv_bfloat16* Bs = As + 2 * 2 * 128 * GK2;

    const int tid = threadIdx.x, lane = tid & 31, warp = tid >> 5;
    const int warpM = warp & 1, warpN = warp >> 1;
    const int g = lane >> 2, tig = lane & 3;
    const int row0 = blockIdx.y * 128, col0 = blockIdx.x * 128;
    const int rA = warpM * 64, cB = warpN * 32;
    const int r0 = tid >> 2, kq = (tid & 3) * 8;
    const int r1 = r0 + 64;

    float acc[4][4][4];
#pragma unroll
    for (int i = 0; i < 4; i++)
#pragma unroll
        for (int j = 0; j < 4; j++)
#pragma unroll
            for (int e = 0; e < 4; e++) acc[i][j][e] = 0.f;

    auto ISSUE = [&](int k0, int st) {
        const __nv_bfloat16 *ph, *pl; int kb;
        if (k0 < 1024) { ph = A0h; pl = A0l; kb = k0; }
        else           { ph = A1h; pl = A1l; kb = k0 - 1024; }
        __nv_bfloat16* Ah = As + (st * 2 + 0) * 128 * GK2;
        __nv_bfloat16* Al = As + (st * 2 + 1) * 128 * GK2;
        __nv_bfloat16* Bh = Bs + (st * 2 + 0) * 128 * GK2;
        __nv_bfloat16* Bl = Bs + (st * 2 + 1) * 128 * GK2;
        cpa16(Ah + r0 * GK2 + kq, ph + (long)(row0 + r0) * 1024 + kb + kq);
        cpa16(Ah + r1 * GK2 + kq, ph + (long)(row0 + r1) * 1024 + kb + kq);
        cpa16(Al + r0 * GK2 + kq, pl + (long)(row0 + r0) * 1024 + kb + kq);
        cpa16(Al + r1 * GK2 + kq, pl + (long)(row0 + r1) * 1024 + kb + kq);
        cpa16(Bh + r0 * GK2 + kq, Bth + (long)(col0 + r0) * 2048 + k0 + kq);
        cpa16(Bh + r1 * GK2 + kq, Bth + (long)(col0 + r1) * 2048 + k0 + kq);
        cpa16(Bl + r0 * GK2 + kq, Btl + (long)(col0 + r0) * 2048 + k0 + kq);
        cpa16(Bl + r1 * GK2 + kq, Btl + (long)(col0 + r1) * 2048 + k0 + kq);
    };

    const int KT = K / 32;
    ISSUE(0, 0); CPA_COMMIT;

    for (int kt = 0; kt < KT; kt++) {
        const int st = kt & 1;
        if (kt + 1 < KT) { ISSUE((kt + 1) * 32, st ^ 1); CPA_COMMIT; CPA_WAIT(1); }
        else             { CPA_WAIT(0); }
        __syncthreads();

        const __nv_bfloat16* Ah = As + (st * 2 + 0) * 128 * GK2;
        const __nv_bfloat16* Al = As + (st * 2 + 1) * 128 * GK2;
        const __nv_bfloat16* Bh = Bs + (st * 2 + 0) * 128 * GK2;
        const __nv_bfloat16* Bl = Bs + (st * 2 + 1) * 128 * GK2;

#pragma unroll
        for (int kk = 0; kk < 32; kk += 16) {
            uint32_t ah[4][4], al[4][4], bh[4][2], bl[4][2];
#pragma unroll
            for (int i = 0; i < 4; i++) {
                int r = rA + i * 16 + g, c = kk + tig * 2;
                ah[i][0] = *(const uint32_t*)&Ah[r * GK2 + c];
                ah[i][1] = *(const uint32_t*)&Ah[(r + 8) * GK2 + c];
                ah[i][2] = *(const uint32_t*)&Ah[r * GK2 + c + 8];
                ah[i][3] = *(const uint32_t*)&Ah[(r + 8) * GK2 + c + 8];
                al[i][0] = *(const uint32_t*)&Al[r * GK2 + c];
                al[i][1] = *(const uint32_t*)&Al[(r + 8) * GK2 + c];
                al[i][2] = *(const uint32_t*)&Al[r * GK2 + c + 8];
                al[i][3] = *(const uint32_t*)&Al[(r + 8) * GK2 + c + 8];
            }
#pragma unroll
            for (int j = 0; j < 4; j++) {
                int n = cB + j * 8 + g, c = kk + tig * 2;
                bh[j][0] = *(const uint32_t*)&Bh[n * GK2 + c];
                bh[j][1] = *(const uint32_t*)&Bh[n * GK2 + c + 8];
                bl[j][0] = *(const uint32_t*)&Bl[n * GK2 + c];
                bl[j][1] = *(const uint32_t*)&Bl[n * GK2 + c + 8];
            }
#pragma unroll
            for (int i = 0; i < 4; i++)
#pragma unroll
                for (int j = 0; j < 4; j++) {
                    mma16816(acc[i][j], ah[i], bh[j]);
                    mma16816(acc[i][j], ah[i], bl[j]);
                    mma16816(acc[i][j], al[i], bh[j]);
                }
        }
        __syncthreads();   // all reads of stage st done before it is reissued
    }

    auto epi2 = [&](long row, int col, float v0, float v1) {
        v0 += bias[col]; v1 += bias[col + 1];
        if (EPI == 0) {
            out[row * (long)ldc + col]     = v0;
            out[row * (long)ldc + col + 1] = v1;
        } else if (EPI == 1) {
            float s0 = 1.f / (1.f + __expf(-v0));
            float s1 = 1.f / (1.f + __expf(-v1));
            if (col < 1024) {
                out[row * 1024 + col]     = s0;
                out[row * 1024 + col + 1] = s1;
            } else {
                int d = col - 1024;
                float rx0 = s0 * X[row * 1024 + d];
                float rx1 = s1 * X[row * 1024 + d + 1];
                __nv_bfloat16 h0 = __float2bfloat16(rx0);
                __nv_bfloat16 h1 = __float2bfloat16(rx1);
                __nv_bfloat162 hp; hp.x = h0; hp.y = h1;
                __nv_bfloat162 lp;
                lp.x = __float2bfloat16(rx0 - __bfloat162float(h0));
                lp.y = __float2bfloat16(rx1 - __bfloat162float(h1));
                *(__nv_bfloat162*)&g_RX_hi[row * 1024 + d] = hp;
                *(__nv_bfloat162*)&g_RX_lo[row * 1024 + d] = lp;
            }
        } else {
            float hc0 = tanhf(v0), hc1 = tanhf(v1);
            float x0 = X[row * 1024 + col], x1 = X[row * 1024 + col + 1];
            out[row * 1024 + col]     = x0 + UD[row * 1024 + col] * (hc0 - x0);
            out[row * 1024 + col + 1] = x1 + UD[row * 1024 + col + 1] * (hc1 - x1);
        }
    };

#pragma unroll
    for (int i = 0; i < 4; i++) {
        long r = row0 + rA + i * 16 + g;
#pragma unroll
        for (int j = 0; j < 4; j++) {
            int cc = col0 + cB + j * 8 + tig * 2;
            epi2(r,     cc, acc[i][j][0], acc[i][j][1]);
            epi2(r + 8, cc, acc[i][j][2], acc[i][j][3]);
        }
    }
}

// ---------------- scan init --------------------------------------------------
__global__ void scan_init(const float* __restrict__ prev_ht)
{
    int i = blockIdx.x * 256 + threadIdx.x;   // 32768
    if (i == 0) g_barcnt = 0;
    float v = prev_ht[i];
    g_hcur[i] = v;
    __nv_bfloat16 hi = __float2bfloat16(v);
    g_h_hi[i] = hi;
    g_h_lo[i] = __float2bfloat16(v - __bfloat162float(hi));
}

__device__ __forceinline__ void gridbar(unsigned target)
{
    __syncthreads();
    if (threadIdx.x == 0) {
        asm volatile("red.release.gpu.global.add.u32 [%0], 1;"
                     :: "l"(&g_barcnt) : "memory");
        unsigned v;
        do {
            asm volatile("ld.acquire.gpu.global.u32 %0, [%1];"
                         : "=r"(v) : "l"(&g_barcnt) : "memory");
        } while (v < target);
    }
    __syncthreads();
}

// ---------------- persistent tensor-core scan (cp.async staging) -------------
extern __shared__ __align__(16) char dsraw[];
__global__ void __launch_bounds__(256, 1)
scan_persistent()
{
    __nv_bfloat16* ws1h = (__nv_bfloat16*)dsraw;
    __nv_bfloat16* ws1l = ws1h + 16 * WSP;
    __nv_bfloat16* ws2h = ws1l + 16 * WSP;
    __nv_bfloat16* ws2l = ws2h + 8 * WSP;
    __nv_bfloat16* hsh0 = ws2l + 8 * WSP;
    __nv_bfloat16* hsl0 = hsh0 + 32 * HSP;
    __nv_bfloat16* hsh1 = hsl0 + 32 * HSP;
    __nv_bfloat16* hsl1 = hsh1 + 32 * HSP;
    float* red = (float*)(hsl1 + 32 * HSP);

    const int tid = threadIdx.x, bx = blockIdx.x;
    const int lane = tid & 31, warp = tid >> 5;
    const int g = lane >> 2, tig = lane & 3;

    // ---- weight slices from pre-split transposed W (once) ----
#pragma unroll
    for (int s = 0; s < 8; s++) {
        int f = tid + s * 256;                 // 0..2047
        int c = f >> 7, q = (f & 127) * 8;
        *(uint4*)(ws1h + c * WSP + q) = *(const uint4*)&g_Wt_hi[(long)(bx * 16 + c) * 2048 + 1024 + q];
        *(uint4*)(ws1l + c * WSP + q) = *(const uint4*)&g_Wt_lo[(long)(bx * 16 + c) * 2048 + 1024 + q];
    }
#pragma unroll
    for (int s = 0; s < 4; s++) {
        int f = tid + s * 256;                 // 0..1023
        int c = f >> 7, q = (f & 127) * 8;
        *(uint4*)(ws2h + c * WSP + q) = *(const uint4*)&g_Wt_hi[(long)(2048 + bx * 8 + c) * 2048 + 1024 + q];
        *(uint4*)(ws2l + c * WSP + q) = *(const uint4*)&g_Wt_lo[(long)(2048 + bx * 8 + c) * 2048 + 1024 + q];
    }
    __syncthreads();

    const int o1 = tid * 2;
    const int r1 = o1 >> 4, c1 = o1 & 15;
    const int col1 = bx * 16 + c1;
    const int r2 = tid >> 3, c2 = tid & 7;
    const int d2 = bx * 8 + c2;

    // staging map: id = tid + s*256 -> r = id>>5, q = (id&31)*8
    const int sr[4] = { tid >> 5, (tid + 256) >> 5, (tid + 512) >> 5, (tid + 768) >> 5 };
    const int sq = (tid & 31) * 8;

    auto ISSUE = [&](const __nv_bfloat16* srcH, const __nv_bfloat16* srcL,
                     int kc, __nv_bfloat16* dh, __nv_bfloat16* dl) {
#pragma unroll
        for (int s = 0; s < 4; s++) {
            int r = sr[s];
            cpa16(dh + r * HSP + sq, srcH + r * 1024 + kc + sq);
            cpa16(dl + r * HSP + sq, srcL + r * 1024 + kc + sq);
        }
        CPA_COMMIT;
    };

    unsigned tgt = NB;

    for (int t = 0; t < TT; t++) {
        // ---- phase-1 staging starts immediately ----
        ISSUE(g_h_hi, g_h_lo, 0, hsh0, hsl0);

        float2 g1 = *(const float2*)&g_gates[((long)r1 * TT + t) * 3072 + col1];
        float2 hv1 = make_float2(0.f, 0.f);
        if (col1 >= 1024)
            hv1 = __ldcg((const float2*)&g_hcur[r1 * 1024 + (col1 - 1024)]);
        float gg2 = g_gates[((long)r2 * TT + t) * 3072 + 2048 + d2];
        float hp = __ldcg(&g_hcur[r2 * 1024 + d2]);

        // ================= phase 1 =================
        float acc[2][2][4];
#pragma unroll
        for (int i = 0; i < 2; i++)
#pragma unroll
            for (int j = 0; j < 2; j++)
#pragma unroll
                for (int e = 0; e < 4; e++) acc[i][j][e] = 0.f;

        for (int ch = 0; ch < 4; ch++) {
            if (ch < 3) {
                ISSUE(g_h_hi, g_h_lo, (ch + 1) * 256,
                      (ch & 1) ? hsh0 : hsh1, (ch & 1) ? hsl0 : hsl1);
                CPA_WAIT(1);
            } else {
                CPA_WAIT(0);
            }
            __syncthreads();
            const __nv_bfloat16* Ah = (ch & 1) ? hsh1 : hsh0;
            const __nv_bfloat16* Al = (ch & 1) ? hsl1 : hsl0;
#pragma unroll
            for (int kk = 0; kk < 32; kk += 16) {
                int kl = warp * 32 + kk + tig * 2;   // chunk-local
                int kg = ch * 256 + kl;              // global k
                uint32_t ah[2][4], al[2][4], bh[2][2], bl[2][2];
#pragma unroll
                for (int i = 0; i < 2; i++) {
                    int r = i * 16 + g;
                    ah[i][0] = *(const uint32_t*)&Ah[r * HSP + kl];
                    ah[i][1] = *(const uint32_t*)&Ah[(r + 8) * HSP + kl];
                    ah[i][2] = *(const uint32_t*)&Ah[r * HSP + kl + 8];
                    ah[i][3] = *(const uint32_t*)&Ah[(r + 8) * HSP + kl + 8];
                    al[i][0] = *(const uint32_t*)&Al[r * HSP + kl];
                    al[i][1] = *(const uint32_t*)&Al[(r + 8) * HSP + kl];
                    al[i][2] = *(const uint32_t*)&Al[r * HSP + kl + 8];
                    al[i][3] = *(const uint32_t*)&Al[(r + 8) * HSP + kl + 8];
                }
#pragma unroll
                for (int j = 0; j < 2; j++) {
                    int n = j * 8 + g;
                    bh[j][0] = *(const uint32_t*)&ws1h[n * WSP + kg];
                    bh[j][1] = *(const uint32_t*)&ws1h[n * WSP + kg + 8];
                    bl[j][0] = *(const uint32_t*)&ws1l[n * WSP + kg];
                    bl[j][1] = *(const uint32_t*)&ws1l[n * WSP + kg + 8];
                }
#pragma unroll
                for (int i = 0; i < 2; i++)
#pragma unroll
                    for (int j = 0; j < 2; j++) {
                        mma16816(acc[i][j], ah[i], bh[j]);
                        mma16816(acc[i][j], ah[i], bl[j]);
                        mma16816(acc[i][j], al[i], bh[j]);
                    }
            }
            __syncthreads();
        }
#pragma unroll
        for (int i = 0; i < 2; i++)
#pragma unroll
            for (int j = 0; j < 2; j++) {
                int r = i * 16 + g, c = j * 8 + tig * 2;
                red[warp * 512 + r * 16 + c]           = acc[i][j][0];
                red[warp * 512 + r * 16 + c + 1]       = acc[i][j][1];
                red[warp * 512 + (r + 8) * 16 + c]     = acc[i][j][2];
                red[warp * 512 + (r + 8) * 16 + c + 1] = acc[i][j][3];
            }
        __syncthreads();
        {
            float v0 = g1.x, v1 = g1.y;
#pragma unroll
            for (int w = 0; w < 8; w++) {
                float2 p = *(const float2*)&red[w * 512 + o1];
                v0 += p.x; v1 += p.y;
            }
            float s0 = 1.f / (1.f + __expf(-v0));
            float s1 = 1.f / (1.f + __expf(-v1));
            if (col1 < 1024) {
                *(float2*)&g_U[r1 * 1024 + col1] = make_float2(s0, s1);
            } else {
                int d = col1 - 1024;
                float rh0 = s0 * hv1.x, rh1 = s1 * hv1.y;
                __nv_bfloat16 h0 = __float2bfloat16(rh0);
                __nv_bfloat16 h1 = __float2bfloat16(rh1);
                __nv_bfloat162 hip; hip.x = h0; hip.y = h1;
                __nv_bfloat162 lop;
                lop.x = __float2bfloat16(rh0 - __bfloat162float(h0));
                lop.y = __float2bfloat16(rh1 - __bfloat162float(h1));
                *(__nv_bfloat162*)&g_rh_hi[r1 * 1024 + d] = hip;
                *(__nv_bfloat162*)&g_rh_lo[r1 * 1024 + d] = lop;
            }
        }

        gridbar(tgt); tgt += NB;

        // ================= phase 2 =================
        ISSUE(g_rh_hi, g_rh_lo, 0, hsh0, hsl0);
        float uu = __ldcg(&g_U[r2 * 1024 + d2]);

        float acc2[2][4];
#pragma unroll
        for (int i = 0; i < 2; i++)
#pragma unroll
            for (int e = 0; e < 4; e++) acc2[i][e] = 0.f;

        for (int ch = 0; ch < 4; ch++) {
            if (ch < 3) {
                ISSUE(g_rh_hi, g_rh_lo, (ch + 1) * 256,
                      (ch & 1) ? hsh0 : hsh1, (ch & 1) ? hsl0 : hsl1);
                CPA_WAIT(1);
            } else {
                CPA_WAIT(0);
            }
            __syncthreads();
            const __nv_bfloat16* Ah = (ch & 1) ? hsh1 : hsh0;
            const __nv_bfloat16* Al = (ch & 1) ? hsl1 : hsl0;
#pragma unroll
            for (int kk = 0; kk < 32; kk += 16) {
                int kl = warp * 32 + kk + tig * 2;
                int kg = ch * 256 + kl;
                uint32_t ah[2][4], al[2][4], bh[2], bl[2];
#pragma unroll
                for (int i = 0; i < 2; i++) {
                    int r = i * 16 + g;
                    ah[i][0] = *(const uint32_t*)&Ah[r * HSP + kl];
                    ah[i][1] = *(const uint32_t*)&Ah[(r + 8) * HSP + kl];
                    ah[i][2] = *(const uint32_t*)&Ah[r * HSP + kl + 8];
                    ah[i][3] = *(const uint32_t*)&Ah[(r + 8) * HSP + kl + 8];
                    al[i][0] = *(const uint32_t*)&Al[r * HSP + kl];
                    al[i][1] = *(const uint32_t*)&Al[(r + 8) * HSP + kl];
                    al[i][2] = *(const uint32_t*)&Al[r * HSP + kl + 8];
                    al[i][3] = *(const uint32_t*)&Al[(r + 8) * HSP + kl + 8];
                }
                {
                    int n = g;
                    bh[0] = *(const uint32_t*)&ws2h[n * WSP + kg];
                    bh[1] = *(const uint32_t*)&ws2h[n * WSP + kg + 8];
                    bl[0] = *(const uint32_t*)&ws2l[n * WSP + kg];
                    bl[1] = *(const uint32_t*)&ws2l[n * WSP + kg + 8];
                }
#pragma unroll
                for (int i = 0; i < 2; i++) {
                    mma16816(acc2[i], ah[i], bh);
                    mma16816(acc2[i], ah[i], bl);
                    mma16816(acc2[i], al[i], bh);
                }
            }
            __syncthreads();
        }
#pragma unroll
        for (int i = 0; i < 2; i++) {
            int r = i * 16 + g, c = tig * 2;
            red[warp * 256 + r * 8 + c]           = acc2[i][0];
            red[warp * 256 + r * 8 + c + 1]       = acc2[i][1];
            red[warp * 256 + (r + 8) * 8 + c]     = acc2[i][2];
            red[warp * 256 + (r + 8) * 8 + c + 1] = acc2[i][3];
        }
        __syncthreads();
        {
            float v = gg2;
#pragma unroll
            for (int w = 0; w < 8; w++) v += red[w * 256 + tid];
            float hc = tanhf(v);
            float hn = hp + uu * (hc - hp);
            g_hcur[r2 * 1024 + d2] = hn;
            __nv_bfloat16 hi = __float2bfloat16(hn);
            __nv_bfloat16 lo = __float2bfloat16(hn - __bfloat162float(hi));
            g_h_hi[r2 * 1024 + d2] = hi;
            g_h_lo[r2 * 1024 + d2] = lo;
            long ho = ((long)r2 * TT + t) * 1024 + d2;
            g_HT_hi[ho] = hi;
            g_HT_lo[ho] = lo;
        }

        gridbar(tgt); tgt += NB;
    }
}

__global__ void copy_last(float* __restrict__ out)
{
    int i = blockIdx.x * 256 + threadIdx.x;   // 32768
    out[i] = g_hcur[i];
}

// ---------------- launch ------------------------------------------------------
#define SCAN_SMEM ((48*WSP + 4*32*HSP) * 2 + 8*512*4)
#define GEMM_SMEM (2 * 2 * 2 * 128 * GK2 * 2)

extern "C" void kernel_launch(void* const* d_in, const int* in_sizes, int n_in,
                              void* d_out, int out_size)
{
    const float* x       = (const float*)d_in[0];
    const float* prev_ht = (const float*)d_in[1];
    const float* weight  = (const float*)d_in[2];
    const float* bias    = (const float*)d_in[3];
    float* out = (float*)d_out;

    float *G, *UD;
    __nv_bfloat16 *Wth, *Wtl, *Xh, *Xl, *HTh, *HTl, *RXh, *RXl;
    cudaGetSymbolAddress((void**)&G,   g_gates);
    cudaGetSymbolAddress((void**)&UD,  g_UD);
    cudaGetSymbolAddress((void**)&Wth, g_Wt_hi);
    cudaGetSymbolAddress((void**)&Wtl, g_Wt_lo);
    cudaGetSymbolAddress((void**)&Xh,  g_X_hi);
    cudaGetSymbolAddress((void**)&Xl,  g_X_lo);
    cudaGetSymbolAddress((void**)&HTh, g_HT_hi);
    cudaGetSymbolAddress((void**)&HTl, g_HT_lo);
    cudaGetSymbolAddress((void**)&RXh, g_RX_hi);
    cudaGetSymbolAddress((void**)&RXl, g_RX_lo);

    static int attr_set = 0;
    if (!attr_set) {
        cudaFuncSetAttribute(scan_persistent,
                             cudaFuncAttributeMaxDynamicSharedMemorySize, SCAN_SMEM);
        cudaFuncSetAttribute(mma_gemm<0>,
                             cudaFuncAttributeMaxDynamicSharedMemorySize, GEMM_SMEM);
        cudaFuncSetAttribute(mma_gemm<1>,
                             cudaFuncAttributeMaxDynamicSharedMemorySize, GEMM_SMEM);
        cudaFuncSetAttribute(mma_gemm<2>,
                             cudaFuncAttributeMaxDynamicSharedMemorySize, GEMM_SMEM);
        attr_set = 1;
    }

    // prep: split W (transposed) and x into bf16 hi/lo
    conv_w_kernel<<<dim3(2048 / 64, 6144 / 64), 256>>>(weight);
    conv_x_kernel<<<MROWS * DD / 8 / 256, 256>>>(x);

    // gates = x @ Wxt + bt
    mma_gemm<0><<<dim3(3072 / 128, MROWS / 128), 256, GEMM_SMEM>>>(
        Xh, Xl, Xh, Xl, Wth, Wtl, bias, nullptr, G, nullptr, 1024, 3072);

    // scan
    scan_init<<<128, 256>>>(prev_ht);
    scan_persistent<<<NB, 256, SCAN_SMEM>>>();

    // F1: sigmoid(bd[:2D] + [x|ht] @ W[:,3072:5120]) -> UD, RX
    mma_gemm<1><<<dim3(2048 / 128, MROWS / 128), 256, GEMM_SMEM>>>(
        Xh, Xl, HTh, HTl, Wth + (size_t)3072 * 2048, Wtl + (size_t)3072 * 2048,
        bias + 3072, x, UD, nullptr, 2048, 2048);

    // F2: tanh(bd[2D:] + [rd*x|ht] @ W[:,5120:6144]); out = x + ud*(hc-x)
    mma_gemm<2><<<dim3(1024 / 128, MROWS / 128), 256, GEMM_SMEM>>>(
        RXh, RXl, HTh, HTl, Wth + (size_t)5120 * 2048, Wtl + (size_t)5120 * 2048,
        bias + 5120, x, out, UD, 2048, 1024);

    // last_ht
    copy_last<<<128, 256>>>(out + (size_t)MROWS * 1024);
}